// round 1
// baseline (speedup 1.0000x reference)
#include <cuda_runtime.h>
#include <math.h>

#define BB 16
#define SS 12
#define NN 2048
#define HH 64
#define HEADS 4
#define DHD 16
#define EE 32768
#define STEPS 12

// ---------------- scratch (static device globals; no allocation) -------------
__device__ float g_y[BB*NN*HH];            // [b][n][64]
__device__ float g_h[BB*HEADS*NN*DHD];     // [b][hd][n][16]
__device__ float g_es[BB*HEADS*NN];        // [b*4+hd][n]
__device__ float g_ed[BB*HEADS*NN];
__device__ float g_k[BB*NN*HH];
__device__ float g_acc[BB*NN*HH];
__device__ int   g_rowoff[NN+1];
__device__ int   g_cnt[NN];
__device__ int   g_cursor[NN];
__device__ int   g_csr[EE];

// ---------------- CSR build --------------------------------------------------
__global__ void k_zero() {
    int i = blockIdx.x*blockDim.x + threadIdx.x;
    if (i < NN) g_cnt[i] = 0;
}

__global__ void k_hist(const int* __restrict__ dst) {
    int e = blockIdx.x*blockDim.x + threadIdx.x;
    if (e < EE) atomicAdd(&g_cnt[dst[e]], 1);
}

__global__ void k_scan() {          // 1 block, 256 threads, 8 elems/thread
    __shared__ int part[256];
    int t = threadIdx.x;
    int base = t*8;
    int loc[8];
    int s = 0;
    #pragma unroll
    for (int i = 0; i < 8; ++i) { loc[i] = s; s += g_cnt[base+i]; }
    part[t] = s;
    __syncthreads();
    for (int off = 1; off < 256; off <<= 1) {
        int v = (t >= off) ? part[t-off] : 0;
        __syncthreads();
        part[t] += v;
        __syncthreads();
    }
    int excl = (t == 0) ? 0 : part[t-1];
    #pragma unroll
    for (int i = 0; i < 8; ++i) {
        int v = excl + loc[i];
        g_rowoff[base+i] = v;
        g_cursor[base+i] = v;
    }
    if (t == 255) g_rowoff[NN] = part[255];
}

__global__ void k_fill(const int* __restrict__ src, const int* __restrict__ dst) {
    int e = blockIdx.x*blockDim.x + threadIdx.x;
    if (e < EE) {
        int p = atomicAdd(&g_cursor[dst[e]], 1);
        g_csr[p] = src[e];
    }
}

// ---------------- input projection: y0 = inputs[:,0] @ w_in + b_in ----------
__global__ void k_input(const float* __restrict__ inp, const float* __restrict__ w_in,
                        const float* __restrict__ b_in) {
    int idx = blockIdx.x*blockDim.x + threadIdx.x;
    if (idx >= BB*NN*HH) return;
    int h  = idx & 63;
    int bn = idx >> 6;
    int b  = bn >> 11;
    int n  = bn & 2047;
    const float* ip = inp + ((size_t)(b*SS + 0)*NN + n)*2;
    g_y[idx] = ip[0]*w_in[h] + ip[1]*w_in[64+h] + b_in[h];
}

// ---------------- stage GEMM: y_eff = y + coef*k ; h = y_eff@Wh ; scores -----
__global__ void __launch_bounds__(256) k_gemm(const float* __restrict__ Wh,
                                              const float* __restrict__ a_src,
                                              const float* __restrict__ a_dst,
                                              float coef) {
    __shared__ float Whs[64*64];
    __shared__ float As[64], Ad[64];
    __shared__ float srow[8][136];
    int t = threadIdx.x;
    for (int i = t; i < 1024; i += 256)
        ((float4*)Whs)[i] = ((const float4*)Wh)[i];
    if (t < 64) { As[t] = a_src[t]; Ad[t] = a_dst[t]; }
    __syncthreads();

    int warp = t >> 5, lane = t & 31, half = lane >> 4, hl = lane & 15;
    float* sr = &srow[warp][half*68];
    int rowbase = blockIdx.x*64 + warp*8;
    int j0 = hl*4;
    int hd = j0 >> 4;
    int dh0 = j0 & 15;

    for (int it = 0; it < 4; ++it) {
        int gr = rowbase + it*2 + half;
        float4 v = ((const float4*)(g_y + (size_t)gr*64))[hl];
        if (coef != 0.f) {
            float4 kv = ((const float4*)(g_k + (size_t)gr*64))[hl];
            v.x += coef*kv.x; v.y += coef*kv.y; v.z += coef*kv.z; v.w += coef*kv.w;
        }
        sr[hl*4+0] = v.x; sr[hl*4+1] = v.y; sr[hl*4+2] = v.z; sr[hl*4+3] = v.w;
        __syncwarp();

        float4 a = make_float4(0.f, 0.f, 0.f, 0.f);
        #pragma unroll 8
        for (int i = 0; i < 64; ++i) {
            float rv = sr[i];
            float4 w4 = ((const float4*)(Whs + i*64))[hl];
            a.x += rv*w4.x; a.y += rv*w4.y; a.z += rv*w4.z; a.w += rv*w4.w;
        }
        int b = gr >> 11, n = gr & 2047;
        // scatter h to [b][hd][n][dh]
        ((float4*)(g_h + (((size_t)(b*HEADS + hd)*NN + n)*DHD + dh0)))[0] = a;
        // attention scores
        float ps = a.x*As[hd*16+dh0] + a.y*As[hd*16+dh0+1] + a.z*As[hd*16+dh0+2] + a.w*As[hd*16+dh0+3];
        float pd = a.x*Ad[hd*16+dh0] + a.y*Ad[hd*16+dh0+1] + a.z*Ad[hd*16+dh0+2] + a.w*Ad[hd*16+dh0+3];
        ps += __shfl_xor_sync(0xffffffffu, ps, 1);
        ps += __shfl_xor_sync(0xffffffffu, ps, 2);
        pd += __shfl_xor_sync(0xffffffffu, pd, 1);
        pd += __shfl_xor_sync(0xffffffffu, pd, 2);
        if ((hl & 3) == 0) {
            int o = (b*HEADS + hd)*NN + n;
            g_es[o] = ps;
            g_ed[o] = pd;
        }
        __syncwarp();
    }
}

// ---------------- edge softmax + aggregation + RK4 bookkeeping ---------------
// grid: 128 blocks = (b, hd, half-of-nodes); 512 threads; smem-staged h slice.
#define DT6F ((float)(0.1/6.0))
#define SMEM_EDGE ((NN*17 + NN + NN + 32*16)*4 + 32*16*4)

__global__ void __launch_bounds__(512) k_edge(const float* __restrict__ bias_g, int mode) {
    extern __shared__ float sm[];
    float* h_sl  = sm;                       // 2048*17
    float* s_sl  = sm + NN*17;               // 2048
    float* d_sl  = s_sl + NN;                // 2048
    float* w_s   = d_sl + NN;                // 16 warps * 32
    int*   src_s = (int*)(w_s + 16*32);      // 16 warps * 32

    int t = threadIdx.x;
    int b  = blockIdx.x >> 3;
    int hd = (blockIdx.x >> 1) & 3;
    int halfblk = blockIdx.x & 1;

    const float4* hp = (const float4*)(g_h + (size_t)(b*HEADS + hd)*NN*DHD);
    for (int i = t; i < NN*DHD/4; i += 512) {
        float4 v = hp[i];
        int e0 = i*4;
        float* d = h_sl + (e0 >> 4)*17 + (e0 & 15);
        d[0] = v.x; d[1] = v.y; d[2] = v.z; d[3] = v.w;
    }
    int sbase = (b*HEADS + hd)*NN;
    for (int i = t; i < NN; i += 512) {
        s_sl[i] = g_es[sbase + i];
        d_sl[i] = g_ed[sbase + i];
    }
    __syncthreads();

    int warp = t >> 5, lane = t & 31;
    int half = lane >> 4, dd = lane & 15;
    float* ws = w_s + warp*32;
    int*   ss = src_s + warp*32;
    float bias = bias_g[hd*16 + dd];
    int nlo = halfblk*1024 + warp*64;

    for (int nn = 0; nn < 64; ++nn) {
        int n  = nlo + nn;
        int r0 = g_rowoff[n];
        int r1 = g_rowoff[n+1];
        float dval = d_sl[n];

        // pass 1: max logit
        float m = -INFINITY;
        for (int c0 = r0; c0 < r1; c0 += 32) {
            int j = c0 + lane;
            if (j < r1) {
                float x = s_sl[g_csr[j]] + dval;
                float lg = (x > 0.f) ? x : 0.2f*x;
                m = fmaxf(m, lg);
            }
        }
        #pragma unroll
        for (int o = 16; o > 0; o >>= 1) m = fmaxf(m, __shfl_xor_sync(0xffffffffu, m, o));

        // pass 2: w = exp(logit - m); ACC = sum w*h[src]; wsum = sum w
        float wsum = 0.f, acc = 0.f;
        for (int c0 = r0; c0 < r1; c0 += 32) {
            int j = c0 + lane;
            float w = 0.f; int s = 0;
            if (j < r1) {
                s = g_csr[j];
                float x = s_sl[s] + dval;
                float lg = (x > 0.f) ? x : 0.2f*x;
                w = __expf(lg - m);
                wsum += w;
            }
            ws[lane] = w; ss[lane] = s;
            __syncwarp();
            int cnt = min(32, r1 - c0);
            for (int p = half; p < cnt; p += 2)
                acc += ws[p] * h_sl[ss[p]*17 + dd];
            __syncwarp();
        }
        #pragma unroll
        for (int o = 16; o > 0; o >>= 1) wsum += __shfl_xor_sync(0xffffffffu, wsum, o);
        acc += __shfl_xor_sync(0xffffffffu, acc, 16);

        if (lane < 16) {
            float inv = (wsum > 0.f) ? 1.0f/wsum : 0.f;
            float kv = acc*inv + bias;
            size_t idx = ((size_t)(b*NN + n))*64 + hd*16 + dd;
            if (mode == 0)      { g_k[idx] = kv; g_acc[idx] = kv; }
            else if (mode == 1) { g_k[idx] = kv; g_acc[idx] += 2.f*kv; }
            else                { g_y[idx] += DT6F*(g_acc[idx] + kv); }
        }
    }
}

// ---------------- output MLP: out = tanh(y@w1+b1)@w2+b2 ----------------------
__global__ void __launch_bounds__(256) k_out(const float* __restrict__ W1, const float* __restrict__ b1,
                                             const float* __restrict__ W2, const float* __restrict__ b2,
                                             float* __restrict__ out) {
    __shared__ float W1s[4096], W2s[4096];
    __shared__ float b1s[64], b2s[64];
    __shared__ float srow[8][136];
    int t = threadIdx.x;
    for (int i = t; i < 1024; i += 256) {
        ((float4*)W1s)[i] = ((const float4*)W1)[i];
        ((float4*)W2s)[i] = ((const float4*)W2)[i];
    }
    if (t < 64) { b1s[t] = b1[t]; b2s[t] = b2[t]; }
    __syncthreads();

    int warp = t >> 5, lane = t & 31, half = lane >> 4, hl = lane & 15;
    float* sr = &srow[warp][half*68];
    int rowbase = blockIdx.x*64 + warp*8;
    int j0 = hl*4;

    for (int it = 0; it < 4; ++it) {
        int gr = rowbase + it*2 + half;
        float4 v = ((const float4*)(g_y + (size_t)gr*64))[hl];
        sr[hl*4+0] = v.x; sr[hl*4+1] = v.y; sr[hl*4+2] = v.z; sr[hl*4+3] = v.w;
        __syncwarp();
        float4 a = make_float4(0.f, 0.f, 0.f, 0.f);
        #pragma unroll 8
        for (int i = 0; i < 64; ++i) {
            float rv = sr[i];
            float4 w4 = ((const float4*)(W1s + i*64))[hl];
            a.x += rv*w4.x; a.y += rv*w4.y; a.z += rv*w4.z; a.w += rv*w4.w;
        }
        a.x = tanhf(a.x + b1s[j0]);
        a.y = tanhf(a.y + b1s[j0+1]);
        a.z = tanhf(a.z + b1s[j0+2]);
        a.w = tanhf(a.w + b1s[j0+3]);
        __syncwarp();
        sr[hl*4+0] = a.x; sr[hl*4+1] = a.y; sr[hl*4+2] = a.z; sr[hl*4+3] = a.w;
        __syncwarp();
        float4 o = make_float4(0.f, 0.f, 0.f, 0.f);
        #pragma unroll 8
        for (int i = 0; i < 64; ++i) {
            float rv = sr[i];
            float4 w4 = ((const float4*)(W2s + i*64))[hl];
            o.x += rv*w4.x; o.y += rv*w4.y; o.z += rv*w4.z; o.w += rv*w4.w;
        }
        o.x += b2s[j0]; o.y += b2s[j0+1]; o.z += b2s[j0+2]; o.w += b2s[j0+3];
        ((float4*)(out + (size_t)gr*64))[hl] = o;
        __syncwarp();
    }
}

// ---------------- launch -----------------------------------------------------
extern "C" void kernel_launch(void* const* d_in, const int* in_sizes, int n_in,
                              void* d_out, int out_size) {
    const float* inputs = (const float*)d_in[0];
    const float* w_in   = (const float*)d_in[1];
    const float* b_in   = (const float*)d_in[2];
    const float* Wh     = (const float*)d_in[3];
    const float* bias_g = (const float*)d_in[4];
    const float* a_src  = (const float*)d_in[5];
    const float* a_dst  = (const float*)d_in[6];
    const float* w1     = (const float*)d_in[7];
    const float* b1     = (const float*)d_in[8];
    const float* w2     = (const float*)d_in[9];
    const float* b2     = (const float*)d_in[10];
    const int*   src    = (const int*)d_in[11];
    const int*   dst    = (const int*)d_in[12];
    float* out = (float*)d_out;

    cudaFuncSetAttribute(k_edge, cudaFuncAttributeMaxDynamicSharedMemorySize, SMEM_EDGE);

    k_zero<<<(NN+255)/256, 256>>>();
    k_hist<<<EE/256, 256>>>(dst);
    k_scan<<<1, 256>>>();
    k_fill<<<EE/256, 256>>>(src, dst);
    k_input<<<(BB*NN*HH)/256, 256>>>(inputs, w_in, b_in);

    const float c2 = 0.05f;   // 0.5*DT
    const float c4 = 0.1f;    // DT
    for (int s = 0; s < STEPS; ++s) {
        k_gemm<<<512, 256>>>(Wh, a_src, a_dst, 0.f);
        k_edge<<<128, 512, SMEM_EDGE>>>(bias_g, 0);
        k_gemm<<<512, 256>>>(Wh, a_src, a_dst, c2);
        k_edge<<<128, 512, SMEM_EDGE>>>(bias_g, 1);
        k_gemm<<<512, 256>>>(Wh, a_src, a_dst, c2);
        k_edge<<<128, 512, SMEM_EDGE>>>(bias_g, 1);
        k_gemm<<<512, 256>>>(Wh, a_src, a_dst, c4);
        k_edge<<<128, 512, SMEM_EDGE>>>(bias_g, 2);
    }
    k_out<<<512, 256>>>(w1, b1, w2, b2, out);
}

// round 2
// speedup vs baseline: 1.5029x; 1.5029x over previous
#include <cuda_runtime.h>
#include <math.h>

#define BB 16
#define SS 12
#define NN 2048
#define HH 64
#define HEADS 4
#define DHD 16
#define EE 32768
#define STEPS 12
#define DT6F ((float)(0.1/6.0))

// ---------------- scratch (static device globals; no allocation) -------------
__device__ float g_y[BB*NN*HH];            // [b][n][64]
__device__ float g_h[BB*HEADS*NN*DHD];     // [b][hd][n][16]
__device__ float g_es[BB*HEADS*NN];        // [b*4+hd][n]
__device__ float g_ed[BB*HEADS*NN];
__device__ float g_k[BB*NN*HH];
__device__ float g_acc[BB*NN*HH];
__device__ int   g_rowoff[NN+1];
__device__ int   g_cnt[NN];
__device__ int   g_cursor[NN];
__device__ int   g_csr[EE];                // src per CSR slot
__device__ int   g_csr_dst[EE];            // dst per CSR slot

// ---------------- f32x2 helpers ----------------------------------------------
__device__ __forceinline__ void fma2(unsigned long long &d, unsigned long long a,
                                     unsigned long long b) {
    asm("fma.rn.f32x2 %0, %1, %2, %0;" : "+l"(d) : "l"(a), "l"(b));
}
__device__ __forceinline__ unsigned long long pack2(float lo, float hi) {
    unsigned long long r;
    asm("mov.b64 %0, {%1,%2};" : "=l"(r) : "f"(lo), "f"(hi));
    return r;
}
__device__ __forceinline__ void unpack2(float &lo, float &hi, unsigned long long v) {
    asm("mov.b64 {%0,%1}, %2;" : "=f"(lo), "=f"(hi) : "l"(v));
}

// ---------------- CSR build --------------------------------------------------
__global__ void k_zero() {
    int i = blockIdx.x*blockDim.x + threadIdx.x;
    if (i < NN) g_cnt[i] = 0;
}
__global__ void k_hist(const int* __restrict__ dst) {
    int e = blockIdx.x*blockDim.x + threadIdx.x;
    if (e < EE) atomicAdd(&g_cnt[dst[e]], 1);
}
__global__ void k_scan() {
    __shared__ int part[256];
    int t = threadIdx.x;
    int base = t*8;
    int loc[8];
    int s = 0;
    #pragma unroll
    for (int i = 0; i < 8; ++i) { loc[i] = s; s += g_cnt[base+i]; }
    part[t] = s;
    __syncthreads();
    for (int off = 1; off < 256; off <<= 1) {
        int v = (t >= off) ? part[t-off] : 0;
        __syncthreads();
        part[t] += v;
        __syncthreads();
    }
    int excl = (t == 0) ? 0 : part[t-1];
    #pragma unroll
    for (int i = 0; i < 8; ++i) {
        int v = excl + loc[i];
        g_rowoff[base+i] = v;
        g_cursor[base+i] = v;
    }
    if (t == 255) g_rowoff[NN] = part[255];
}
__global__ void k_fill(const int* __restrict__ src, const int* __restrict__ dst) {
    int e = blockIdx.x*blockDim.x + threadIdx.x;
    if (e < EE) {
        int d = dst[e];
        int p = atomicAdd(&g_cursor[d], 1);
        g_csr[p] = src[e];
        g_csr_dst[p] = d;
    }
}

// ---------------- input projection -------------------------------------------
__global__ void k_input(const float* __restrict__ inp, const float* __restrict__ w_in,
                        const float* __restrict__ b_in) {
    int idx = blockIdx.x*blockDim.x + threadIdx.x;
    if (idx >= BB*NN*HH) return;
    int h  = idx & 63;
    int bn = idx >> 6;
    int b  = bn >> 11;
    int n  = bn & 2047;
    const float* ip = inp + ((size_t)(b*SS + 0)*NN + n)*2;
    g_y[idx] = ip[0]*w_in[h] + ip[1]*w_in[64+h] + b_in[h];
}

// ---------------- stage GEMM (f32x2): h = (y+coef*k)@Wh ; scores -------------
// dynamic smem: sdup[8 warps][8 rows][64] ull, Whs[4096] f32, As[64], Ad[64]
#define SMEM_GEMM (8*8*64*8 + 4096*4 + 128*4)

__global__ void __launch_bounds__(256) k_gemm(const float* __restrict__ Wh,
                                              const float* __restrict__ a_src,
                                              const float* __restrict__ a_dst,
                                              float coef) {
    extern __shared__ unsigned long long smg[];
    unsigned long long* sdup = smg;                   // 8*8*64
    float* Whs = (float*)(smg + 8*8*64);              // 4096
    float* As  = Whs + 4096;                          // 64
    float* Ad  = As + 64;                             // 64

    int t = threadIdx.x, warp = t >> 5, lane = t & 31;
    int half = lane >> 4, hl = lane & 15;

    for (int i = t; i < 1024; i += 256)
        ((float4*)Whs)[i] = ((const float4*)Wh)[i];
    if (t < 64) { As[t] = a_src[t]; Ad[t] = a_dst[t]; }

    int rowbase = blockIdx.x*64 + warp*8;
    unsigned long long* sw = sdup + warp*8*64;

    // stage 8 rows, duplicated as f32x2 {v,v}
    #pragma unroll
    for (int q = 0; q < 4; ++q) {
        int li = lane*4 + q;            // 0..127 over 8 rows x 16 float4
        int r = li >> 4, c4 = li & 15;
        float4 v = ((const float4*)(g_y + (size_t)(rowbase + r)*64))[c4];
        if (coef != 0.f) {
            float4 kv = ((const float4*)(g_k + (size_t)(rowbase + r)*64))[c4];
            v.x += coef*kv.x; v.y += coef*kv.y; v.z += coef*kv.z; v.w += coef*kv.w;
        }
        unsigned long long* d = sw + r*64 + c4*4;
        d[0] = pack2(v.x, v.x); d[1] = pack2(v.y, v.y);
        d[2] = pack2(v.z, v.z); d[3] = pack2(v.w, v.w);
    }
    __syncthreads();

    unsigned long long acc[4][2];
    #pragma unroll
    for (int r = 0; r < 4; ++r) { acc[r][0] = 0ull; acc[r][1] = 0ull; }

    const unsigned long long* rowp = sw + (half*4)*64;

    #pragma unroll 4
    for (int i = 0; i < 64; ++i) {
        ulonglong2 wp = *((const ulonglong2*)(Whs + i*64 + hl*4));
        #pragma unroll
        for (int r = 0; r < 4; ++r) {
            unsigned long long rv = rowp[r*64 + i];
            fma2(acc[r][0], rv, wp.x);
            fma2(acc[r][1], rv, wp.y);
        }
    }

    int j0 = hl*4;
    int hd = hl >> 2, dh0 = (hl & 3)*4;
    float4 av = *(const float4*)(As + j0);
    float4 dv4 = *(const float4*)(Ad + j0);

    #pragma unroll
    for (int r = 0; r < 4; ++r) {
        float4 a;
        unpack2(a.x, a.y, acc[r][0]);
        unpack2(a.z, a.w, acc[r][1]);
        int gr = rowbase + half*4 + r;
        int b = gr >> 11, n = gr & 2047;
        *(float4*)(g_h + (((size_t)(b*HEADS + hd)*NN + n)*DHD + dh0)) = a;
        float ps = a.x*av.x + a.y*av.y + a.z*av.z + a.w*av.w;
        float pd = a.x*dv4.x + a.y*dv4.y + a.z*dv4.z + a.w*dv4.w;
        ps += __shfl_xor_sync(0xffffffffu, ps, 1);
        ps += __shfl_xor_sync(0xffffffffu, ps, 2);
        pd += __shfl_xor_sync(0xffffffffu, pd, 1);
        pd += __shfl_xor_sync(0xffffffffu, pd, 2);
        if ((hl & 3) == 0) {
            int o = (b*HEADS + hd)*NN + n;
            g_es[o] = ps;
            g_ed[o] = pd;
        }
    }
}

// ---------------- edge softmax + aggregation + RK4 bookkeeping ---------------
// smem floats: h 2048*17 | s 2048 | d 1024 | red 32 | w W_CAP
#define W_CAP 20160
#define SMEM_EDGE ((2048*17 + 2048 + 1024 + 32 + W_CAP)*4)

__global__ void __launch_bounds__(512) k_edge(const float* __restrict__ bias_g, int mode) {
    extern __shared__ float sm[];
    float* h_sl = sm;                    // 2048*17
    float* s_sl = h_sl + 2048*17;        // 2048
    float* d_sl = s_sl + 2048;           // 1024
    float* red  = d_sl + 1024;           // 32
    float* w_sl = red + 32;              // W_CAP

    int t = threadIdx.x;
    int b  = blockIdx.x >> 3;
    int hd = (blockIdx.x >> 1) & 3;
    int halfblk = blockIdx.x & 1;
    int n0 = halfblk*1024;
    int sbase = (b*HEADS + hd)*NN;

    // stage h slice (padded stride 17)
    const float4* hp = (const float4*)(g_h + (size_t)sbase*DHD);
    for (int i = t; i < NN*DHD/4; i += 512) {
        float4 v = hp[i];
        int e0 = i*4;
        float* d = h_sl + (e0 >> 4)*17 + (e0 & 15);
        d[0] = v.x; d[1] = v.y; d[2] = v.z; d[3] = v.w;
    }
    // stage scores + block max of src scores
    float lm = -INFINITY;
    for (int i = t; i < NN; i += 512) {
        float v = g_es[sbase + i];
        s_sl[i] = v;
        lm = fmaxf(lm, v);
    }
    for (int i = t; i < 1024; i += 512) d_sl[i] = g_ed[sbase + n0 + i];
    #pragma unroll
    for (int o = 16; o > 0; o >>= 1) lm = fmaxf(lm, __shfl_xor_sync(0xffffffffu, lm, o));
    if ((t & 31) == 0) red[t >> 5] = lm;
    __syncthreads();
    if (t == 0) {
        float S = red[0];
        #pragma unroll
        for (int i = 1; i < 16; ++i) S = fmaxf(S, red[i]);
        red[16] = S;
    }
    __syncthreads();
    float S = red[16];

    int e0 = g_rowoff[n0], e1 = g_rowoff[n0 + 1024];

    // phase B: per-edge weights, full lane parallelism, no atomics.
    // m_n = leaky(S + d_n) >= leaky(s + d_n) for all s -> exp in (0,1], exact softmax.
    for (int j = e0 + t; j < e1; j += 512) {
        int s  = g_csr[j];
        int dl = g_csr_dst[j] - n0;
        float dv = d_sl[dl];
        float x  = s_sl[s] + dv;
        float lg = (x > 0.f) ? x : 0.2f*x;
        float xm = S + dv;
        float m  = (xm > 0.f) ? xm : 0.2f*xm;
        w_sl[j - e0] = __expf(lg - m);
    }
    __syncthreads();

    // phase C: half-warp per node gather
    int warp = t >> 5, lane = t & 31;
    int halfw = lane >> 4, dd = lane & 15;
    float bias = bias_g[hd*16 + dd];

    for (int k = 0; k < 32; ++k) {
        int n  = n0 + warp*64 + k*2 + halfw;
        int r0 = g_rowoff[n];
        int r1 = g_rowoff[n+1];
        float acc = 0.f, wsum = 0.f;
        int j = r0;
        for (; j + 4 <= r1; j += 4) {
            float w0 = w_sl[j   - e0], w1 = w_sl[j+1 - e0];
            float w2 = w_sl[j+2 - e0], w3 = w_sl[j+3 - e0];
            int s0 = g_csr[j],   s1 = g_csr[j+1];
            int s2 = g_csr[j+2], s3 = g_csr[j+3];
            acc += w0*h_sl[s0*17 + dd];
            acc += w1*h_sl[s1*17 + dd];
            acc += w2*h_sl[s2*17 + dd];
            acc += w3*h_sl[s3*17 + dd];
            wsum += w0 + w1 + w2 + w3;
        }
        for (; j < r1; ++j) {
            float w = w_sl[j - e0];
            int s = g_csr[j];
            acc += w*h_sl[s*17 + dd];
            wsum += w;
        }
        float inv = (wsum > 0.f) ? 1.0f/wsum : 0.f;
        float kv = acc*inv + bias;
        size_t idx = ((size_t)(b*NN + n))*64 + hd*16 + dd;
        if (mode == 0)      { g_k[idx] = kv; g_acc[idx] = kv; }
        else if (mode == 1) { g_k[idx] = kv; g_acc[idx] += 2.f*kv; }
        else                { g_y[idx] += DT6F*(g_acc[idx] + kv); }
    }
}

// ---------------- output MLP -------------------------------------------------
__global__ void __launch_bounds__(256) k_out(const float* __restrict__ W1, const float* __restrict__ b1,
                                             const float* __restrict__ W2, const float* __restrict__ b2,
                                             float* __restrict__ out) {
    __shared__ float W1s[4096], W2s[4096];
    __shared__ float b1s[64], b2s[64];
    __shared__ float srow[8][136];
    int t = threadIdx.x;
    for (int i = t; i < 1024; i += 256) {
        ((float4*)W1s)[i] = ((const float4*)W1)[i];
        ((float4*)W2s)[i] = ((const float4*)W2)[i];
    }
    if (t < 64) { b1s[t] = b1[t]; b2s[t] = b2[t]; }
    __syncthreads();

    int warp = t >> 5, lane = t & 31, half = lane >> 4, hl = lane & 15;
    float* sr = &srow[warp][half*68];
    int rowbase = blockIdx.x*64 + warp*8;
    int j0 = hl*4;

    for (int it = 0; it < 4; ++it) {
        int gr = rowbase + it*2 + half;
        float4 v = ((const float4*)(g_y + (size_t)gr*64))[hl];
        sr[hl*4+0] = v.x; sr[hl*4+1] = v.y; sr[hl*4+2] = v.z; sr[hl*4+3] = v.w;
        __syncwarp();
        float4 a = make_float4(0.f, 0.f, 0.f, 0.f);
        #pragma unroll 8
        for (int i = 0; i < 64; ++i) {
            float rv = sr[i];
            float4 w4 = ((const float4*)(W1s + i*64))[hl];
            a.x += rv*w4.x; a.y += rv*w4.y; a.z += rv*w4.z; a.w += rv*w4.w;
        }
        a.x = tanhf(a.x + b1s[j0]);
        a.y = tanhf(a.y + b1s[j0+1]);
        a.z = tanhf(a.z + b1s[j0+2]);
        a.w = tanhf(a.w + b1s[j0+3]);
        __syncwarp();
        sr[hl*4+0] = a.x; sr[hl*4+1] = a.y; sr[hl*4+2] = a.z; sr[hl*4+3] = a.w;
        __syncwarp();
        float4 o = make_float4(0.f, 0.f, 0.f, 0.f);
        #pragma unroll 8
        for (int i = 0; i < 64; ++i) {
            float rv = sr[i];
            float4 w4 = ((const float4*)(W2s + i*64))[hl];
            o.x += rv*w4.x; o.y += rv*w4.y; o.z += rv*w4.z; o.w += rv*w4.w;
        }
        o.x += b2s[j0]; o.y += b2s[j0+1]; o.z += b2s[j0+2]; o.w += b2s[j0+3];
        ((float4*)(out + (size_t)gr*64))[hl] = o;
        __syncwarp();
    }
}

// ---------------- launch -----------------------------------------------------
extern "C" void kernel_launch(void* const* d_in, const int* in_sizes, int n_in,
                              void* d_out, int out_size) {
    const float* inputs = (const float*)d_in[0];
    const float* w_in   = (const float*)d_in[1];
    const float* b_in   = (const float*)d_in[2];
    const float* Wh     = (const float*)d_in[3];
    const float* bias_g = (const float*)d_in[4];
    const float* a_src  = (const float*)d_in[5];
    const float* a_dst  = (const float*)d_in[6];
    const float* w1     = (const float*)d_in[7];
    const float* b1     = (const float*)d_in[8];
    const float* w2     = (const float*)d_in[9];
    const float* b2     = (const float*)d_in[10];
    const int*   src    = (const int*)d_in[11];
    const int*   dst    = (const int*)d_in[12];
    float* out = (float*)d_out;

    cudaFuncSetAttribute(k_edge, cudaFuncAttributeMaxDynamicSharedMemorySize, SMEM_EDGE);
    cudaFuncSetAttribute(k_gemm, cudaFuncAttributeMaxDynamicSharedMemorySize, SMEM_GEMM);

    k_zero<<<(NN+255)/256, 256>>>();
    k_hist<<<EE/256, 256>>>(dst);
    k_scan<<<1, 256>>>();
    k_fill<<<EE/256, 256>>>(src, dst);
    k_input<<<(BB*NN*HH)/256, 256>>>(inputs, w_in, b_in);

    const float c2 = 0.05f;   // 0.5*DT
    const float c4 = 0.1f;    // DT
    for (int s = 0; s < STEPS; ++s) {
        k_gemm<<<512, 256, SMEM_GEMM>>>(Wh, a_src, a_dst, 0.f);
        k_edge<<<128, 512, SMEM_EDGE>>>(bias_g, 0);
        k_gemm<<<512, 256, SMEM_GEMM>>>(Wh, a_src, a_dst, c2);
        k_edge<<<128, 512, SMEM_EDGE>>>(bias_g, 1);
        k_gemm<<<512, 256, SMEM_GEMM>>>(Wh, a_src, a_dst, c2);
        k_edge<<<128, 512, SMEM_EDGE>>>(bias_g, 1);
        k_gemm<<<512, 256, SMEM_GEMM>>>(Wh, a_src, a_dst, c4);
        k_edge<<<128, 512, SMEM_EDGE>>>(bias_g, 2);
    }
    k_out<<<512, 256>>>(w1, b1, w2, b2, out);
}

// round 3
// speedup vs baseline: 2.2862x; 1.5212x over previous
#include <cuda_runtime.h>
#include <math.h>

#define BB 16
#define SS 12
#define NN 2048
#define HH 64
#define HEADS 4
#define DHD 16
#define EE 32768
#define STEPS 12
#define DT6F ((float)(0.1/6.0))

// ---------------- scratch ----------------------------------------------------
__device__ float g_y[BB*NN*HH];
__device__ float g_h[BB*HEADS*NN*DHD];     // [b][hd][n][16]
__device__ float g_es[BB*HEADS*NN];
__device__ float g_ed[BB*HEADS*NN];
__device__ float g_k[BB*NN*HH];
__device__ float g_acc[BB*NN*HH];
__device__ int   g_rowoff[NN+1];
__device__ int   g_cnt[NN];
__device__ int   g_cursor[NN];
__device__ unsigned short g_csr16[EE];     // src per CSR slot
__device__ unsigned short g_csrd16[EE];    // dst per CSR slot

// ---------------- f32x2 helpers ----------------------------------------------
__device__ __forceinline__ void fma2(unsigned long long &d, unsigned long long a,
                                     unsigned long long b) {
    asm("fma.rn.f32x2 %0, %1, %2, %0;" : "+l"(d) : "l"(a), "l"(b));
}
__device__ __forceinline__ unsigned long long pack2(float lo, float hi) {
    unsigned long long r;
    asm("mov.b64 %0, {%1,%2};" : "=l"(r) : "f"(lo), "f"(hi));
    return r;
}
__device__ __forceinline__ void unpack2(float &lo, float &hi, unsigned long long v) {
    asm("mov.b64 {%0,%1}, %2;" : "=f"(lo), "=f"(hi) : "l"(v));
}

// ---------------- CSR build --------------------------------------------------
__global__ void k_zero() {
    int i = blockIdx.x*blockDim.x + threadIdx.x;
    if (i < NN) g_cnt[i] = 0;
}
__global__ void k_hist(const int* __restrict__ dst) {
    int e = blockIdx.x*blockDim.x + threadIdx.x;
    if (e < EE) atomicAdd(&g_cnt[dst[e]], 1);
}
__global__ void k_scan() {
    __shared__ int part[256];
    int t = threadIdx.x;
    int base = t*8;
    int loc[8];
    int s = 0;
    #pragma unroll
    for (int i = 0; i < 8; ++i) { loc[i] = s; s += g_cnt[base+i]; }
    part[t] = s;
    __syncthreads();
    for (int off = 1; off < 256; off <<= 1) {
        int v = (t >= off) ? part[t-off] : 0;
        __syncthreads();
        part[t] += v;
        __syncthreads();
    }
    int excl = (t == 0) ? 0 : part[t-1];
    #pragma unroll
    for (int i = 0; i < 8; ++i) {
        int v = excl + loc[i];
        g_rowoff[base+i] = v;
        g_cursor[base+i] = v;
    }
    if (t == 255) g_rowoff[NN] = part[255];
}
__global__ void k_fill(const int* __restrict__ src, const int* __restrict__ dst) {
    int e = blockIdx.x*blockDim.x + threadIdx.x;
    if (e < EE) {
        int d = dst[e];
        int p = atomicAdd(&g_cursor[d], 1);
        g_csr16[p]  = (unsigned short)src[e];
        g_csrd16[p] = (unsigned short)d;
    }
}

// ---------------- input projection -------------------------------------------
__global__ void k_input(const float* __restrict__ inp, const float* __restrict__ w_in,
                        const float* __restrict__ b_in) {
    int idx = blockIdx.x*blockDim.x + threadIdx.x;
    if (idx >= BB*NN*HH) return;
    int h  = idx & 63;
    int bn = idx >> 6;
    int b  = bn >> 11;
    int n  = bn & 2047;
    const float* ip = inp + ((size_t)(b*SS + 0)*NN + n)*2;
    g_y[idx] = ip[0]*w_in[h] + ip[1]*w_in[64+h] + b_in[h];
}

// ---------------- stage GEMM (f32x2): h = (y+coef*k)@Wh ; scores -------------
#define SMEM_GEMM (8*8*64*8 + 4096*4 + 128*4)

__global__ void __launch_bounds__(256) k_gemm(const float* __restrict__ Wh,
                                              const float* __restrict__ a_src,
                                              const float* __restrict__ a_dst,
                                              float coef) {
    extern __shared__ unsigned long long smg[];
    unsigned long long* sdup = smg;                   // 8*8*64
    float* Whs = (float*)(smg + 8*8*64);              // 4096
    float* As  = Whs + 4096;
    float* Ad  = As + 64;

    int t = threadIdx.x, warp = t >> 5, lane = t & 31;
    int half = lane >> 4, hl = lane & 15;

    for (int i = t; i < 1024; i += 256)
        ((float4*)Whs)[i] = ((const float4*)Wh)[i];
    if (t < 64) { As[t] = a_src[t]; Ad[t] = a_dst[t]; }

    int rowbase = blockIdx.x*64 + warp*8;
    unsigned long long* sw = sdup + warp*8*64;

    #pragma unroll
    for (int q = 0; q < 4; ++q) {
        int li = lane*4 + q;
        int r = li >> 4, c4 = li & 15;
        float4 v = ((const float4*)(g_y + (size_t)(rowbase + r)*64))[c4];
        if (coef != 0.f) {
            float4 kv = ((const float4*)(g_k + (size_t)(rowbase + r)*64))[c4];
            v.x += coef*kv.x; v.y += coef*kv.y; v.z += coef*kv.z; v.w += coef*kv.w;
        }
        unsigned long long* d = sw + r*64 + c4*4;
        d[0] = pack2(v.x, v.x); d[1] = pack2(v.y, v.y);
        d[2] = pack2(v.z, v.z); d[3] = pack2(v.w, v.w);
    }
    __syncthreads();

    unsigned long long acc[4][2];
    #pragma unroll
    for (int r = 0; r < 4; ++r) { acc[r][0] = 0ull; acc[r][1] = 0ull; }

    const unsigned long long* rowp = sw + (half*4)*64;

    #pragma unroll 4
    for (int i = 0; i < 64; ++i) {
        ulonglong2 wp = *((const ulonglong2*)(Whs + i*64 + hl*4));
        #pragma unroll
        for (int r = 0; r < 4; ++r) {
            unsigned long long rv = rowp[r*64 + i];
            fma2(acc[r][0], rv, wp.x);
            fma2(acc[r][1], rv, wp.y);
        }
    }

    int j0 = hl*4;
    int hd = hl >> 2, dh0 = (hl & 3)*4;
    float4 av = *(const float4*)(As + j0);
    float4 dv4 = *(const float4*)(Ad + j0);

    #pragma unroll
    for (int r = 0; r < 4; ++r) {
        float4 a;
        unpack2(a.x, a.y, acc[r][0]);
        unpack2(a.z, a.w, acc[r][1]);
        int gr = rowbase + half*4 + r;
        int b = gr >> 11, n = gr & 2047;
        *(float4*)(g_h + (((size_t)(b*HEADS + hd)*NN + n)*DHD + dh0)) = a;
        float ps = a.x*av.x + a.y*av.y + a.z*av.z + a.w*av.w;
        float pd = a.x*dv4.x + a.y*dv4.y + a.z*dv4.z + a.w*dv4.w;
        ps += __shfl_xor_sync(0xffffffffu, ps, 1);
        ps += __shfl_xor_sync(0xffffffffu, ps, 2);
        pd += __shfl_xor_sync(0xffffffffu, pd, 1);
        pd += __shfl_xor_sync(0xffffffffu, pd, 2);
        if ((hl & 3) == 0) {
            int o = (b*HEADS + hd)*NN + n;
            g_es[o] = ps;
            g_ed[o] = pd;
        }
    }
}

// ---------------- edge softmax + aggregation + RK4 bookkeeping ---------------
// smem: h 2048*17 f | s 2048 f | d 1024 f | roff 1026 i | red 34 f | wp 17408 u
#define W_CAP 17408
#define SMEM_EDGE ((2048*17 + 2048 + 1024 + 1026 + 34 + W_CAP)*4)

__global__ void __launch_bounds__(1024) k_edge(const float* __restrict__ bias_g, int mode) {
    extern __shared__ float sm[];
    float* h_sl = sm;                          // 2048*17
    float* s_sl = h_sl + 2048*17;              // 2048
    float* d_sl = s_sl + 2048;                 // 1024
    int*   roff = (int*)(d_sl + 1024);         // 1026
    float* red  = (float*)(roff + 1026);       // 34
    unsigned int* wp = (unsigned int*)(red + 34);  // 17408

    int t = threadIdx.x;
    int b  = blockIdx.x >> 3;
    int hd = (blockIdx.x >> 1) & 3;
    int halfblk = blockIdx.x & 1;
    int n0 = halfblk*1024;
    int sbase = (b*HEADS + hd)*NN;

    int e0 = g_rowoff[n0];
    int e1 = g_rowoff[n0 + 1024];

    // ---- phase A: stage h (pad 17), scores, rowoff; block max of src scores
    const float4* hp = (const float4*)(g_h + (size_t)sbase*DHD);
    for (int i = t; i < NN*DHD/4; i += 1024) {
        float4 v = hp[i];
        int p0 = i*4;
        float* d = h_sl + (p0 >> 4)*17 + (p0 & 15);
        d[0] = v.x; d[1] = v.y; d[2] = v.z; d[3] = v.w;
    }
    float lm = -INFINITY;
    for (int i = t; i < NN; i += 1024) {
        float v = g_es[sbase + i];
        s_sl[i] = v;
        lm = fmaxf(lm, v);
    }
    if (t < 1024) d_sl[t] = g_ed[sbase + n0 + t];
    for (int i = t; i <= 1024; i += 1024) roff[i] = g_rowoff[n0 + i] - e0;
    #pragma unroll
    for (int o = 16; o > 0; o >>= 1) lm = fmaxf(lm, __shfl_xor_sync(0xffffffffu, lm, o));
    if ((t & 31) == 0) red[t >> 5] = lm;
    __syncthreads();
    if (t == 0) {
        float S = red[0];
        #pragma unroll
        for (int i = 1; i < 32; ++i) S = fmaxf(S, red[i]);
        red[32] = S;
    }
    __syncthreads();
    float S = red[32];

    // ---- phase B: per-edge weight, packed (w[31:11] | src[10:0]) ------------
    for (int j = e0 + t; j < e1; j += 1024) {
        int s  = g_csr16[j];
        int dl = g_csrd16[j] - n0;
        float dv = d_sl[dl];
        float x  = s_sl[s] + dv;
        float lg = (x > 0.f) ? x : 0.2f*x;
        float xm = S + dv;
        float m  = (xm > 0.f) ? xm : 0.2f*xm;
        float w  = __expf(lg - m);
        unsigned int bits = (__float_as_uint(w) + 0x400u) & 0xFFFFF800u;
        wp[j - e0] = bits | (unsigned int)s;
    }
    __syncthreads();

    // ---- phase C: half-warp per node; pure-smem gather -----------------------
    int warp = t >> 5, lane = t & 31;
    int halfw = lane >> 4, dd = lane & 15;
    float bias = bias_g[hd*16 + dd];
    const float* hdd = h_sl + dd;

    for (int k = 0; k < 16; ++k) {
        int nl = warp*32 + k*2 + halfw;           // local node 0..1023
        int j  = roff[nl];
        int r1 = roff[nl+1];
        float accA = 0.f, accB = 0.f, wsA = 0.f, wsB = 0.f;
        for (; j + 4 <= r1; j += 4) {
            unsigned int p0 = wp[j],   p1 = wp[j+1];
            unsigned int p2 = wp[j+2], p3 = wp[j+3];
            float w0 = __uint_as_float(p0 & 0xFFFFF800u);
            float w1 = __uint_as_float(p1 & 0xFFFFF800u);
            float w2 = __uint_as_float(p2 & 0xFFFFF800u);
            float w3 = __uint_as_float(p3 & 0xFFFFF800u);
            int s0 = p0 & 0x7FF, s1 = p1 & 0x7FF;
            int s2 = p2 & 0x7FF, s3 = p3 & 0x7FF;
            accA = fmaf(w0, hdd[s0*17], accA);
            accB = fmaf(w1, hdd[s1*17], accB);
            accA = fmaf(w2, hdd[s2*17], accA);
            accB = fmaf(w3, hdd[s3*17], accB);
            wsA += w0 + w1;
            wsB += w2 + w3;
        }
        for (; j < r1; ++j) {
            unsigned int p = wp[j];
            float w = __uint_as_float(p & 0xFFFFF800u);
            accA = fmaf(w, hdd[(p & 0x7FF)*17], accA);
            wsA += w;
        }
        float acc  = accA + accB;
        float wsum = wsA + wsB;
        float inv = (wsum > 0.f) ? 1.0f/wsum : 0.f;
        float kv = acc*inv + bias;
        int n = n0 + nl;
        size_t idx = ((size_t)(b*NN + n))*64 + hd*16 + dd;
        if (mode == 0)      { g_k[idx] = kv; g_acc[idx] = kv; }
        else if (mode == 1) { g_k[idx] = kv; g_acc[idx] += 2.f*kv; }
        else                { g_y[idx] += DT6F*(g_acc[idx] + kv); }
    }
}

// ---------------- output MLP -------------------------------------------------
__global__ void __launch_bounds__(256) k_out(const float* __restrict__ W1, const float* __restrict__ b1,
                                             const float* __restrict__ W2, const float* __restrict__ b2,
                                             float* __restrict__ out) {
    __shared__ float W1s[4096], W2s[4096];
    __shared__ float b1s[64], b2s[64];
    __shared__ float srow[8][136];
    int t = threadIdx.x;
    for (int i = t; i < 1024; i += 256) {
        ((float4*)W1s)[i] = ((const float4*)W1)[i];
        ((float4*)W2s)[i] = ((const float4*)W2)[i];
    }
    if (t < 64) { b1s[t] = b1[t]; b2s[t] = b2[t]; }
    __syncthreads();

    int warp = t >> 5, lane = t & 31, half = lane >> 4, hl = lane & 15;
    float* sr = &srow[warp][half*68];
    int rowbase = blockIdx.x*64 + warp*8;
    int j0 = hl*4;

    for (int it = 0; it < 4; ++it) {
        int gr = rowbase + it*2 + half;
        float4 v = ((const float4*)(g_y + (size_t)gr*64))[hl];
        sr[hl*4+0] = v.x; sr[hl*4+1] = v.y; sr[hl*4+2] = v.z; sr[hl*4+3] = v.w;
        __syncwarp();
        float4 a = make_float4(0.f, 0.f, 0.f, 0.f);
        #pragma unroll 8
        for (int i = 0; i < 64; ++i) {
            float rv = sr[i];
            float4 w4 = ((const float4*)(W1s + i*64))[hl];
            a.x += rv*w4.x; a.y += rv*w4.y; a.z += rv*w4.z; a.w += rv*w4.w;
        }
        a.x = tanhf(a.x + b1s[j0]);
        a.y = tanhf(a.y + b1s[j0+1]);
        a.z = tanhf(a.z + b1s[j0+2]);
        a.w = tanhf(a.w + b1s[j0+3]);
        __syncwarp();
        sr[hl*4+0] = a.x; sr[hl*4+1] = a.y; sr[hl*4+2] = a.z; sr[hl*4+3] = a.w;
        __syncwarp();
        float4 o = make_float4(0.f, 0.f, 0.f, 0.f);
        #pragma unroll 8
        for (int i = 0; i < 64; ++i) {
            float rv = sr[i];
            float4 w4 = ((const float4*)(W2s + i*64))[hl];
            o.x += rv*w4.x; o.y += rv*w4.y; o.z += rv*w4.z; o.w += rv*w4.w;
        }
        o.x += b2s[j0]; o.y += b2s[j0+1]; o.z += b2s[j0+2]; o.w += b2s[j0+3];
        ((float4*)(out + (size_t)gr*64))[hl] = o;
        __syncwarp();
    }
}

// ---------------- launch -----------------------------------------------------
extern "C" void kernel_launch(void* const* d_in, const int* in_sizes, int n_in,
                              void* d_out, int out_size) {
    const float* inputs = (const float*)d_in[0];
    const float* w_in   = (const float*)d_in[1];
    const float* b_in   = (const float*)d_in[2];
    const float* Wh     = (const float*)d_in[3];
    const float* bias_g = (const float*)d_in[4];
    const float* a_src  = (const float*)d_in[5];
    const float* a_dst  = (const float*)d_in[6];
    const float* w1     = (const float*)d_in[7];
    const float* b1     = (const float*)d_in[8];
    const float* w2     = (const float*)d_in[9];
    const float* b2     = (const float*)d_in[10];
    const int*   src    = (const int*)d_in[11];
    const int*   dst    = (const int*)d_in[12];
    float* out = (float*)d_out;

    cudaFuncSetAttribute(k_edge, cudaFuncAttributeMaxDynamicSharedMemorySize, SMEM_EDGE);
    cudaFuncSetAttribute(k_gemm, cudaFuncAttributeMaxDynamicSharedMemorySize, SMEM_GEMM);

    k_zero<<<(NN+255)/256, 256>>>();
    k_hist<<<EE/256, 256>>>(dst);
    k_scan<<<1, 256>>>();
    k_fill<<<EE/256, 256>>>(src, dst);
    k_input<<<(BB*NN*HH)/256, 256>>>(inputs, w_in, b_in);

    const float c2 = 0.05f;
    const float c4 = 0.1f;
    for (int s = 0; s < STEPS; ++s) {
        k_gemm<<<512, 256, SMEM_GEMM>>>(Wh, a_src, a_dst, 0.f);
        k_edge<<<128, 1024, SMEM_EDGE>>>(bias_g, 0);
        k_gemm<<<512, 256, SMEM_GEMM>>>(Wh, a_src, a_dst, c2);
        k_edge<<<128, 1024, SMEM_EDGE>>>(bias_g, 1);
        k_gemm<<<512, 256, SMEM_GEMM>>>(Wh, a_src, a_dst, c2);
        k_edge<<<128, 1024, SMEM_EDGE>>>(bias_g, 1);
        k_gemm<<<512, 256, SMEM_GEMM>>>(Wh, a_src, a_dst, c4);
        k_edge<<<128, 1024, SMEM_EDGE>>>(bias_g, 2);
    }
    k_out<<<512, 256>>>(w1, b1, w2, b2, out);
}

// round 5
// speedup vs baseline: 2.5356x; 1.1091x over previous
#include <cuda_runtime.h>
#include <math.h>

#define BB 16
#define SS 12
#define NN 2048
#define HH 64
#define HEADS 4
#define DHD 16
#define EE 32768
#define STEPS 12
#define DT6F ((float)(0.1/6.0))

// ---------------- scratch ----------------------------------------------------
__device__ float g_y[BB*NN*HH];
__device__ float g_h[BB*HEADS*NN*DHD];     // [b][hd][n][16]
__device__ float g_es[BB*HEADS*NN];
__device__ float g_ed[BB*HEADS*NN];
__device__ float g_k[BB*NN*HH];
__device__ float g_acc[BB*NN*HH];
__device__ int   g_rowoff[NN+1];
__device__ int   g_cnt[NN];
__device__ int   g_cursor[NN];
__device__ int   g_order[NN];              // per-half degree-sorted local node ids
__device__ unsigned short g_csr16[EE];
__device__ unsigned short g_csrd16[EE];

// ---------------- f32x2 helpers ----------------------------------------------
__device__ __forceinline__ void fma2(unsigned long long &d, unsigned long long a,
                                     unsigned long long b) {
    asm("fma.rn.f32x2 %0, %1, %2, %0;" : "+l"(d) : "l"(a), "l"(b));
}
__device__ __forceinline__ unsigned long long pack2(float lo, float hi) {
    unsigned long long r;
    asm("mov.b64 %0, {%1,%2};" : "=l"(r) : "f"(lo), "f"(hi));
    return r;
}
__device__ __forceinline__ void unpack2(float &lo, float &hi, unsigned long long v) {
    asm("mov.b64 {%0,%1}, %2;" : "=f"(lo), "=f"(hi) : "l"(v));
}

// ---------------- input projection + counter zero ----------------------------
__global__ void k_input(const float* __restrict__ inp, const float* __restrict__ w_in,
                        const float* __restrict__ b_in) {
    int idx = blockIdx.x*blockDim.x + threadIdx.x;
    if (idx < NN) g_cnt[idx] = 0;
    if (idx >= BB*NN*HH) return;
    int h  = idx & 63;
    int bn = idx >> 6;
    int b  = bn >> 11;
    int n  = bn & 2047;
    const float* ip = inp + ((size_t)(b*SS + 0)*NN + n)*2;
    g_y[idx] = ip[0]*w_in[h] + ip[1]*w_in[64+h] + b_in[h];
}

__global__ void k_hist(const int* __restrict__ dst) {
    int e = blockIdx.x*blockDim.x + threadIdx.x;
    if (e < EE) atomicAdd(&g_cnt[dst[e]], 1);
}

// scan + degree-sort (single block, 256 threads)
__global__ void k_scan() {
    __shared__ int part[256];
    __shared__ int dh[2][64];       // degree histogram per half
    int t = threadIdx.x;
    if (t < 128) { dh[0][t & 63] = 0; dh[1][t & 63] = 0; }
    int base = t*8;
    int loc[8];
    int s = 0;
    #pragma unroll
    for (int i = 0; i < 8; ++i) { loc[i] = s; s += g_cnt[base+i]; }
    part[t] = s;
    __syncthreads();
    for (int off = 1; off < 256; off <<= 1) {
        int v = (t >= off) ? part[t-off] : 0;
        __syncthreads();
        part[t] += v;
        __syncthreads();
    }
    int excl = (t == 0) ? 0 : part[t-1];
    #pragma unroll
    for (int i = 0; i < 8; ++i) {
        int v = excl + loc[i];
        g_rowoff[base+i] = v;
        g_cursor[base+i] = v;
    }
    if (t == 255) g_rowoff[NN] = part[255];
    // degree histogram
    #pragma unroll
    for (int i = 0; i < 8; ++i) {
        int n = base + i;
        int d = min(g_cnt[n], 63);
        atomicAdd(&dh[n >> 10][d], 1);
    }
    __syncthreads();
    if (t < 2) {                       // exclusive prefix per half
        int acc = 0;
        for (int d = 0; d < 64; ++d) { int c = dh[t][d]; dh[t][d] = acc; acc += c; }
    }
    __syncthreads();
    #pragma unroll
    for (int i = 0; i < 8; ++i) {
        int n = base + i;
        int half = n >> 10;
        int d = min(g_cnt[n], 63);
        int pos = atomicAdd(&dh[half][d], 1);
        g_order[half*1024 + pos] = n & 1023;
    }
}

__global__ void k_fill(const int* __restrict__ src, const int* __restrict__ dst) {
    int e = blockIdx.x*blockDim.x + threadIdx.x;
    if (e < EE) {
        int d = dst[e];
        int p = atomicAdd(&g_cursor[d], 1);
        g_csr16[p]  = (unsigned short)src[e];
        g_csrd16[p] = (unsigned short)d;
    }
}

// ---------------- stage GEMM (f32x2): h = (y+coef*k)@Wh ; scores -------------
#define SMEM_GEMM (8*8*64*8 + 4096*4 + 128*4)

__global__ void __launch_bounds__(256) k_gemm(const float* __restrict__ Wh,
                                              const float* __restrict__ a_src,
                                              const float* __restrict__ a_dst,
                                              float coef) {
    extern __shared__ unsigned long long smg[];
    unsigned long long* sdup = smg;                   // 8*8*64
    float* Whs = (float*)(smg + 8*8*64);              // 4096
    float* As  = Whs + 4096;
    float* Ad  = As + 64;

    int t = threadIdx.x, warp = t >> 5, lane = t & 31;
    int half = lane >> 4, hl = lane & 15;

    for (int i = t; i < 1024; i += 256)
        ((float4*)Whs)[i] = ((const float4*)Wh)[i];
    if (t < 64) { As[t] = a_src[t]; Ad[t] = a_dst[t]; }

    int rowbase = blockIdx.x*64 + warp*8;
    unsigned long long* sw = sdup + warp*8*64;

    #pragma unroll
    for (int q = 0; q < 4; ++q) {
        int li = lane*4 + q;
        int r = li >> 4, c4 = li & 15;
        float4 v = ((const float4*)(g_y + (size_t)(rowbase + r)*64))[c4];
        if (coef != 0.f) {
            float4 kv = ((const float4*)(g_k + (size_t)(rowbase + r)*64))[c4];
            v.x += coef*kv.x; v.y += coef*kv.y; v.z += coef*kv.z; v.w += coef*kv.w;
        }
        unsigned long long* d = sw + r*64 + c4*4;
        d[0] = pack2(v.x, v.x); d[1] = pack2(v.y, v.y);
        d[2] = pack2(v.z, v.z); d[3] = pack2(v.w, v.w);
    }
    __syncthreads();

    unsigned long long acc[4][2];
    #pragma unroll
    for (int r = 0; r < 4; ++r) { acc[r][0] = 0ull; acc[r][1] = 0ull; }

    const unsigned long long* rowp = sw + (half*4)*64;

    #pragma unroll 4
    for (int i = 0; i < 64; ++i) {
        ulonglong2 wpv = *((const ulonglong2*)(Whs + i*64 + hl*4));
        #pragma unroll
        for (int r = 0; r < 4; ++r) {
            unsigned long long rv = rowp[r*64 + i];
            fma2(acc[r][0], rv, wpv.x);
            fma2(acc[r][1], rv, wpv.y);
        }
    }

    int j0 = hl*4;
    int hd = hl >> 2, dh0 = (hl & 3)*4;
    float4 av = *(const float4*)(As + j0);
    float4 dv4 = *(const float4*)(Ad + j0);

    #pragma unroll
    for (int r = 0; r < 4; ++r) {
        float4 a;
        unpack2(a.x, a.y, acc[r][0]);
        unpack2(a.z, a.w, acc[r][1]);
        int gr = rowbase + half*4 + r;
        int b = gr >> 11, n = gr & 2047;
        *(float4*)(g_h + (((size_t)(b*HEADS + hd)*NN + n)*DHD + dh0)) = a;
        float ps = a.x*av.x + a.y*av.y + a.z*av.z + a.w*av.w;
        float pd = a.x*dv4.x + a.y*dv4.y + a.z*dv4.z + a.w*dv4.w;
        ps += __shfl_xor_sync(0xffffffffu, ps, 1);
        ps += __shfl_xor_sync(0xffffffffu, ps, 2);
        pd += __shfl_xor_sync(0xffffffffu, pd, 1);
        pd += __shfl_xor_sync(0xffffffffu, pd, 2);
        if ((hl & 3) == 0) {
            int o = (b*HEADS + hd)*NN + n;
            g_es[o] = ps;
            g_ed[o] = pd;
        }
    }
}

// ---------------- edge softmax + aggregation + RK4 bookkeeping ---------------
// smem words: h 2048*18 | s 2048 | d 1024 | roff 1025 | red 33 | wp 17024
#define W_CAP 17024
#define SMEM_EDGE ((2048*18 + 2048 + 1024 + 1025 + 33 + W_CAP)*4)

__global__ void __launch_bounds__(1024) k_edge(const float* __restrict__ bias_g, int mode) {
    extern __shared__ float sm[];
    float* h_sl = sm;                          // 2048*18 (pad 18, 8B-aligned pairs)
    float* s_sl = h_sl + 2048*18;              // 2048
    float* d_sl = s_sl + 2048;                 // 1024
    int*   roff = (int*)(d_sl + 1024);         // 1025
    float* red  = (float*)(roff + 1025);       // 33
    unsigned int* wp = (unsigned int*)(red + 33);  // 17024

    int t = threadIdx.x;
    int b  = blockIdx.x >> 3;
    int hd = (blockIdx.x >> 1) & 3;
    int halfblk = blockIdx.x & 1;
    int n0 = halfblk*1024;
    int sbase = (b*HEADS + hd)*NN;

    int e0 = g_rowoff[n0];
    int e1 = g_rowoff[n0 + 1024];

    // ---- phase A: stage h (pad 18), scores, rowoff; block max of src scores
    const float4* hp = (const float4*)(g_h + (size_t)sbase*DHD);
    for (int i = t; i < NN*DHD/4; i += 1024) {
        float4 v = hp[i];
        int p0 = i*4;
        float2* d = (float2*)(h_sl + (p0 >> 4)*18 + (p0 & 15));
        d[0] = make_float2(v.x, v.y);
        d[1] = make_float2(v.z, v.w);
    }
    float lm = -INFINITY;
    for (int i = t; i < NN; i += 1024) {
        float v = g_es[sbase + i];
        s_sl[i] = v;
        lm = fmaxf(lm, v);
    }
    d_sl[t] = g_ed[sbase + n0 + t];
    roff[t] = g_rowoff[n0 + t] - e0;
    if (t == 0) roff[1024] = e1 - e0;          // FIX: last entry was unwritten in R4
    #pragma unroll
    for (int o = 16; o > 0; o >>= 1) lm = fmaxf(lm, __shfl_xor_sync(0xffffffffu, lm, o));
    if ((t & 31) == 0) red[t >> 5] = lm;
    __syncthreads();
    if (t == 0) {
        float S = red[0];
        #pragma unroll
        for (int i = 1; i < 32; ++i) S = fmaxf(S, red[i]);
        red[32] = S;
    }
    __syncthreads();
    float S = red[32];

    // ---- phase B: per-edge weight, packed (w[31:11] | src[10:0]) ------------
    for (int j = e0 + t; j < e1; j += 1024) {
        int s  = g_csr16[j];
        int dl = g_csrd16[j] - n0;
        float dv = d_sl[dl];
        float x  = s_sl[s] + dv;
        float lg = (x > 0.f) ? x : 0.2f*x;
        float xm = S + dv;
        float m  = (xm > 0.f) ? xm : 0.2f*xm;
        float w  = __expf(lg - m);
        unsigned int bits = (__float_as_uint(w) + 0x400u) & 0xFFFFF800u;
        wp[j - e0] = bits | (unsigned int)s;
    }
    __syncthreads();

    // ---- phase C: 8 lanes per node (f32x2), degree-sorted groups ------------
    int warp = t >> 5, lane = t & 31;
    int g  = lane >> 3;             // group 0..3
    int l8 = lane & 7;              // dd pair index
    float2 bias2 = *(const float2*)(bias_g + hd*16 + 2*l8);
    const float* hbase = h_sl + 2*l8;

    for (int k = 0; k < 8; ++k) {
        int idx = k*128 + warp*4 + g;            // sorted index 0..1023
        int nl  = g_order[n0 + idx];             // local node id
        int j   = roff[nl];
        int r1  = roff[nl+1];
        unsigned long long a0 = 0ull, a1 = 0ull;
        float ws = 0.f;
        for (; j + 2 <= r1; j += 2) {
            unsigned int p0 = wp[j], p1 = wp[j+1];
            float w0 = __uint_as_float(p0 & 0xFFFFF800u);
            float w1 = __uint_as_float(p1 & 0xFFFFF800u);
            int s0 = p0 & 0x7FF, s1 = p1 & 0x7FF;
            unsigned long long h0 = *(const unsigned long long*)(hbase + s0*18);
            unsigned long long h1 = *(const unsigned long long*)(hbase + s1*18);
            fma2(a0, pack2(w0, w0), h0);
            fma2(a1, pack2(w1, w1), h1);
            ws += w0 + w1;
        }
        if (j < r1) {
            unsigned int p0 = wp[j];
            float w0 = __uint_as_float(p0 & 0xFFFFF800u);
            int s0 = p0 & 0x7FF;
            unsigned long long h0 = *(const unsigned long long*)(hbase + s0*18);
            fma2(a0, pack2(w0, w0), h0);
            ws += w0;
        }
        float ax, ay, bx, by;
        unpack2(ax, ay, a0);
        unpack2(bx, by, a1);
        float inv = (ws > 0.f) ? 1.0f/ws : 0.f;
        float kvx = (ax + bx)*inv + bias2.x;
        float kvy = (ay + by)*inv + bias2.y;
        int n = n0 + nl;
        size_t o = ((size_t)(b*NN + n))*64 + hd*16 + 2*l8;
        if (mode == 0) {
            *(float2*)(g_k + o)   = make_float2(kvx, kvy);
            *(float2*)(g_acc + o) = make_float2(kvx, kvy);
        } else if (mode == 1) {
            *(float2*)(g_k + o) = make_float2(kvx, kvy);
            float2 ac = *(float2*)(g_acc + o);
            *(float2*)(g_acc + o) = make_float2(ac.x + 2.f*kvx, ac.y + 2.f*kvy);
        } else {
            float2 ac = *(float2*)(g_acc + o);
            float2 yv = *(float2*)(g_y + o);
            *(float2*)(g_y + o) = make_float2(yv.x + DT6F*(ac.x + kvx),
                                              yv.y + DT6F*(ac.y + kvy));
        }
    }
}

// ---------------- output MLP -------------------------------------------------
__global__ void __launch_bounds__(256) k_out(const float* __restrict__ W1, const float* __restrict__ b1,
                                             const float* __restrict__ W2, const float* __restrict__ b2,
                                             float* __restrict__ out) {
    __shared__ float W1s[4096], W2s[4096];
    __shared__ float b1s[64], b2s[64];
    __shared__ float srow[8][136];
    int t = threadIdx.x;
    for (int i = t; i < 1024; i += 256) {
        ((float4*)W1s)[i] = ((const float4*)W1)[i];
        ((float4*)W2s)[i] = ((const float4*)W2)[i];
    }
    if (t < 64) { b1s[t] = b1[t]; b2s[t] = b2[t]; }
    __syncthreads();

    int warp = t >> 5, lane = t & 31, half = lane >> 4, hl = lane & 15;
    float* sr = &srow[warp][half*68];
    int rowbase = blockIdx.x*64 + warp*8;
    int j0 = hl*4;

    for (int it = 0; it < 4; ++it) {
        int gr = rowbase + it*2 + half;
        float4 v = ((const float4*)(g_y + (size_t)gr*64))[hl];
        sr[hl*4+0] = v.x; sr[hl*4+1] = v.y; sr[hl*4+2] = v.z; sr[hl*4+3] = v.w;
        __syncwarp();
        float4 a = make_float4(0.f, 0.f, 0.f, 0.f);
        #pragma unroll 8
        for (int i = 0; i < 64; ++i) {
            float rv = sr[i];
            float4 w4 = ((const float4*)(W1s + i*64))[hl];
            a.x += rv*w4.x; a.y += rv*w4.y; a.z += rv*w4.z; a.w += rv*w4.w;
        }
        a.x = tanhf(a.x + b1s[j0]);
        a.y = tanhf(a.y + b1s[j0+1]);
        a.z = tanhf(a.z + b1s[j0+2]);
        a.w = tanhf(a.w + b1s[j0+3]);
        __syncwarp();
        sr[hl*4+0] = a.x; sr[hl*4+1] = a.y; sr[hl*4+2] = a.z; sr[hl*4+3] = a.w;
        __syncwarp();
        float4 o = make_float4(0.f, 0.f, 0.f, 0.f);
        #pragma unroll 8
        for (int i = 0; i < 64; ++i) {
            float rv = sr[i];
            float4 w4 = ((const float4*)(W2s + i*64))[hl];
            o.x += rv*w4.x; o.y += rv*w4.y; o.z += rv*w4.z; o.w += rv*w4.w;
        }
        o.x += b2s[j0]; o.y += b2s[j0+1]; o.z += b2s[j0+2]; o.w += b2s[j0+3];
        ((float4*)(out + (size_t)gr*64))[hl] = o;
        __syncwarp();
    }
}

// ---------------- launch -----------------------------------------------------
extern "C" void kernel_launch(void* const* d_in, const int* in_sizes, int n_in,
                              void* d_out, int out_size) {
    const float* inputs = (const float*)d_in[0];
    const float* w_in   = (const float*)d_in[1];
    const float* b_in   = (const float*)d_in[2];
    const float* Wh     = (const float*)d_in[3];
    const float* bias_g = (const float*)d_in[4];
    const float* a_src  = (const float*)d_in[5];
    const float* a_dst  = (const float*)d_in[6];
    const float* w1     = (const float*)d_in[7];
    const float* b1     = (const float*)d_in[8];
    const float* w2     = (const float*)d_in[9];
    const float* b2     = (const float*)d_in[10];
    const int*   src    = (const int*)d_in[11];
    const int*   dst    = (const int*)d_in[12];
    float* out = (float*)d_out;

    cudaFuncSetAttribute(k_edge, cudaFuncAttributeMaxDynamicSharedMemorySize, SMEM_EDGE);
    cudaFuncSetAttribute(k_gemm, cudaFuncAttributeMaxDynamicSharedMemorySize, SMEM_GEMM);

    // order chosen so profiled launch slot = first k_gemm (diagnostic)
    k_input<<<(BB*NN*HH)/256, 256>>>(inputs, w_in, b_in);   // also zeros g_cnt
    k_hist<<<EE/256, 256>>>(dst);
    k_scan<<<1, 256>>>();
    k_gemm<<<512, 256, SMEM_GEMM>>>(Wh, a_src, a_dst, 0.f);
    k_fill<<<EE/256, 256>>>(src, dst);

    const float c2 = 0.05f;
    const float c4 = 0.1f;
    for (int s = 0; s < STEPS; ++s) {
        if (s != 0) k_gemm<<<512, 256, SMEM_GEMM>>>(Wh, a_src, a_dst, 0.f);
        k_edge<<<128, 1024, SMEM_EDGE>>>(bias_g, 0);
        k_gemm<<<512, 256, SMEM_GEMM>>>(Wh, a_src, a_dst, c2);
        k_edge<<<128, 1024, SMEM_EDGE>>>(bias_g, 1);
        k_gemm<<<512, 256, SMEM_GEMM>>>(Wh, a_src, a_dst, c2);
        k_edge<<<128, 1024, SMEM_EDGE>>>(bias_g, 1);
        k_gemm<<<512, 256, SMEM_GEMM>>>(Wh, a_src, a_dst, c4);
        k_edge<<<128, 1024, SMEM_EDGE>>>(bias_g, 2);
    }
    k_out<<<512, 256>>>(w1, b1, w2, b2, out);
}

// round 6
// speedup vs baseline: 2.8193x; 1.1119x over previous
#include <cuda_runtime.h>
#include <math.h>

#define BB 16
#define SS 12
#define NN 2048
#define HH 64
#define HEADS 4
#define DHD 16
#define EE 32768
#define STEPS 12
#define DT6F ((float)(0.1/6.0))

// ---------------- scratch ----------------------------------------------------
__device__ float g_y[BB*NN*HH];
__device__ float g_h[BB*HEADS*NN*DHD];     // [b][hd][n][16]
__device__ float g_es[BB*HEADS*NN];
__device__ float g_ed[BB*HEADS*NN];
__device__ float g_k[BB*NN*HH];
__device__ float g_acc[BB*NN*HH];
__device__ int   g_rowoff[NN+1];
__device__ int   g_cnt[NN];
__device__ int   g_cursor[NN];
__device__ int   g_order[NN];              // per-half degree-sorted local node ids
__device__ unsigned short g_csr16[EE];
__device__ unsigned short g_csrd16[EE];

// ---------------- f32x2 helpers ----------------------------------------------
__device__ __forceinline__ void fma2(unsigned long long &d, unsigned long long a,
                                     unsigned long long b) {
    asm("fma.rn.f32x2 %0, %1, %2, %0;" : "+l"(d) : "l"(a), "l"(b));
}
__device__ __forceinline__ void add2(unsigned long long &d, unsigned long long a) {
    asm("add.rn.f32x2 %0, %0, %1;" : "+l"(d) : "l"(a));
}
__device__ __forceinline__ unsigned long long pack2(float lo, float hi) {
    unsigned long long r;
    asm("mov.b64 %0, {%1,%2};" : "=l"(r) : "f"(lo), "f"(hi));
    return r;
}
__device__ __forceinline__ void unpack2(float &lo, float &hi, unsigned long long v) {
    asm("mov.b64 {%0,%1}, %2;" : "=f"(lo), "=f"(hi) : "l"(v));
}

// ---------------- input projection + counter zero ----------------------------
__global__ void k_input(const float* __restrict__ inp, const float* __restrict__ w_in,
                        const float* __restrict__ b_in) {
    int idx = blockIdx.x*blockDim.x + threadIdx.x;
    if (idx < NN) g_cnt[idx] = 0;
    if (idx >= BB*NN*HH) return;
    int h  = idx & 63;
    int bn = idx >> 6;
    int b  = bn >> 11;
    int n  = bn & 2047;
    const float* ip = inp + ((size_t)(b*SS + 0)*NN + n)*2;
    g_y[idx] = ip[0]*w_in[h] + ip[1]*w_in[64+h] + b_in[h];
}

__global__ void k_hist(const int* __restrict__ dst) {
    int e = blockIdx.x*blockDim.x + threadIdx.x;
    if (e < EE) atomicAdd(&g_cnt[dst[e]], 1);
}

// scan + degree-sort (single block, 256 threads)
__global__ void k_scan() {
    __shared__ int part[256];
    __shared__ int dh[2][64];
    int t = threadIdx.x;
    if (t < 128) { dh[0][t & 63] = 0; dh[1][t & 63] = 0; }
    int base = t*8;
    int loc[8];
    int s = 0;
    #pragma unroll
    for (int i = 0; i < 8; ++i) { loc[i] = s; s += g_cnt[base+i]; }
    part[t] = s;
    __syncthreads();
    for (int off = 1; off < 256; off <<= 1) {
        int v = (t >= off) ? part[t-off] : 0;
        __syncthreads();
        part[t] += v;
        __syncthreads();
    }
    int excl = (t == 0) ? 0 : part[t-1];
    #pragma unroll
    for (int i = 0; i < 8; ++i) {
        int v = excl + loc[i];
        g_rowoff[base+i] = v;
        g_cursor[base+i] = v;
    }
    if (t == 255) g_rowoff[NN] = part[255];
    #pragma unroll
    for (int i = 0; i < 8; ++i) {
        int n = base + i;
        int d = min(g_cnt[n], 63);
        atomicAdd(&dh[n >> 10][d], 1);
    }
    __syncthreads();
    if (t < 2) {
        int acc = 0;
        for (int d = 0; d < 64; ++d) { int c = dh[t][d]; dh[t][d] = acc; acc += c; }
    }
    __syncthreads();
    #pragma unroll
    for (int i = 0; i < 8; ++i) {
        int n = base + i;
        int half = n >> 10;
        int d = min(g_cnt[n], 63);
        int pos = atomicAdd(&dh[half][d], 1);
        g_order[half*1024 + pos] = n & 1023;
    }
}

__global__ void k_fill(const int* __restrict__ src, const int* __restrict__ dst) {
    int e = blockIdx.x*blockDim.x + threadIdx.x;
    if (e < EE) {
        int d = dst[e];
        int p = atomicAdd(&g_cursor[d], 1);
        g_csr16[p]  = (unsigned short)src[e];
        g_csrd16[p] = (unsigned short)d;
    }
}

// ---------------- stage GEMM v3 (split-K, f32x2) -----------------------------
// 512 threads: warps 0-7 do K[0:32), warps 8-15 do K[32:64) for the SAME 64 rows.
// smem: sdup 4096 ull | partial 2048 ull | Whs 4096 f | As 64 | Ad 64
#define SMEM_GEMM (4096*8 + 2048*8 + 4096*4 + 128*4)

__global__ void __launch_bounds__(512) k_gemm(const float* __restrict__ Wh,
                                              const float* __restrict__ a_src,
                                              const float* __restrict__ a_dst,
                                              float coef) {
    extern __shared__ unsigned long long smg[];
    unsigned long long* sdup    = smg;                 // 64 rows x 64 i (dup f32x2)
    unsigned long long* partial = smg + 4096;          // 64 rows x 32 col-pairs
    float* Whs = (float*)(smg + 4096 + 2048);          // 4096
    float* As  = Whs + 4096;
    float* Ad  = As + 64;

    int t = threadIdx.x, warp = t >> 5, lane = t & 31;
    int half = lane >> 4, hl = lane & 15;
    int kh = warp >> 3, w8 = warp & 7;
    int rowbase = blockIdx.x*64;

    // stage Wh (each thread 8 floats = 2 float4)
    for (int i = t; i < 1024; i += 512)
        ((float4*)Whs)[i] = ((const float4*)Wh)[i];
    if (t < 64) { As[t] = a_src[t]; Ad[t] = a_dst[t]; }

    // stage 64 rows duplicated: thread covers row r = t>>3, i in [ (t&7)*8, +8 )
    {
        int r  = t >> 3;
        int i0 = (t & 7)*8;
        const float4* yp = (const float4*)(g_y + (size_t)(rowbase + r)*64 + i0);
        float4 v0 = yp[0], v1 = yp[1];
        if (coef != 0.f) {
            const float4* kp = (const float4*)(g_k + (size_t)(rowbase + r)*64 + i0);
            float4 k0 = kp[0], k1 = kp[1];
            v0.x += coef*k0.x; v0.y += coef*k0.y; v0.z += coef*k0.z; v0.w += coef*k0.w;
            v1.x += coef*k1.x; v1.y += coef*k1.y; v1.z += coef*k1.z; v1.w += coef*k1.w;
        }
        unsigned long long* d = sdup + r*64 + i0;
        d[0] = pack2(v0.x, v0.x); d[1] = pack2(v0.y, v0.y);
        d[2] = pack2(v0.z, v0.z); d[3] = pack2(v0.w, v0.w);
        d[4] = pack2(v1.x, v1.x); d[5] = pack2(v1.y, v1.y);
        d[6] = pack2(v1.z, v1.z); d[7] = pack2(v1.w, v1.w);
    }
    __syncthreads();

    unsigned long long acc[4][2];
    #pragma unroll
    for (int r = 0; r < 4; ++r) { acc[r][0] = 0ull; acc[r][1] = 0ull; }

    int rl0 = w8*8 + half*4;                 // first of this thread's 4 local rows
    const unsigned long long* rowp = sdup + rl0*64;
    int i0 = kh*32;

    #pragma unroll 4
    for (int ii = 0; ii < 32; ++ii) {
        int i = i0 + ii;
        ulonglong2 wpv = *((const ulonglong2*)(Whs + i*64 + hl*4));
        #pragma unroll
        for (int r = 0; r < 4; ++r) {
            unsigned long long rv = rowp[r*64 + i];
            fma2(acc[r][0], rv, wpv.x);
            fma2(acc[r][1], rv, wpv.y);
        }
    }

    // combine split-K partials through smem
    if (kh == 1) {
        #pragma unroll
        for (int r = 0; r < 4; ++r) {
            partial[(rl0 + r)*32 + hl*2 + 0] = acc[r][0];
            partial[(rl0 + r)*32 + hl*2 + 1] = acc[r][1];
        }
    }
    __syncthreads();
    if (kh == 1) return;

    #pragma unroll
    for (int r = 0; r < 4; ++r) {
        add2(acc[r][0], partial[(rl0 + r)*32 + hl*2 + 0]);
        add2(acc[r][1], partial[(rl0 + r)*32 + hl*2 + 1]);
    }

    int j0 = hl*4;
    int hd = hl >> 2, dh0 = (hl & 3)*4;
    float4 av = *(const float4*)(As + j0);
    float4 dv4 = *(const float4*)(Ad + j0);

    #pragma unroll
    for (int r = 0; r < 4; ++r) {
        float4 a;
        unpack2(a.x, a.y, acc[r][0]);
        unpack2(a.z, a.w, acc[r][1]);
        int gr = rowbase + rl0 + r;
        int b = gr >> 11, n = gr & 2047;
        *(float4*)(g_h + (((size_t)(b*HEADS + hd)*NN + n)*DHD + dh0)) = a;
        float ps = a.x*av.x + a.y*av.y + a.z*av.z + a.w*av.w;
        float pd = a.x*dv4.x + a.y*dv4.y + a.z*dv4.z + a.w*dv4.w;
        ps += __shfl_xor_sync(0xffffffffu, ps, 1);
        ps += __shfl_xor_sync(0xffffffffu, ps, 2);
        pd += __shfl_xor_sync(0xffffffffu, pd, 1);
        pd += __shfl_xor_sync(0xffffffffu, pd, 2);
        if ((hl & 3) == 0) {
            int o = (b*HEADS + hd)*NN + n;
            g_es[o] = ps;
            g_ed[o] = pd;
        }
    }
}

// ---------------- edge softmax + aggregation + RK4 bookkeeping ---------------
// smem words: h 2048*18 | s 2048 | d 1024 | roff 1025 | red 33 | wp 17024
#define W_CAP 17024
#define SMEM_EDGE ((2048*18 + 2048 + 1024 + 1025 + 33 + W_CAP)*4)

__global__ void __launch_bounds__(1024) k_edge(const float* __restrict__ bias_g, int mode) {
    extern __shared__ float sm[];
    float* h_sl = sm;                          // 2048*18
    float* s_sl = h_sl + 2048*18;              // 2048
    float* d_sl = s_sl + 2048;                 // 1024
    int*   roff = (int*)(d_sl + 1024);         // 1025
    float* red  = (float*)(roff + 1025);       // 33
    unsigned int* wp = (unsigned int*)(red + 33);  // 17024

    int t = threadIdx.x;
    int b  = blockIdx.x >> 3;
    int hd = (blockIdx.x >> 1) & 3;
    int halfblk = blockIdx.x & 1;
    int n0 = halfblk*1024;
    int sbase = (b*HEADS + hd)*NN;

    int e0 = g_rowoff[n0];
    int e1 = g_rowoff[n0 + 1024];

    // ---- phase A
    const float4* hp = (const float4*)(g_h + (size_t)sbase*DHD);
    for (int i = t; i < NN*DHD/4; i += 1024) {
        float4 v = hp[i];
        int p0 = i*4;
        float2* d = (float2*)(h_sl + (p0 >> 4)*18 + (p0 & 15));
        d[0] = make_float2(v.x, v.y);
        d[1] = make_float2(v.z, v.w);
    }
    float lm = -INFINITY;
    for (int i = t; i < NN; i += 1024) {
        float v = g_es[sbase + i];
        s_sl[i] = v;
        lm = fmaxf(lm, v);
    }
    d_sl[t] = g_ed[sbase + n0 + t];
    roff[t] = g_rowoff[n0 + t] - e0;
    if (t == 0) roff[1024] = e1 - e0;
    #pragma unroll
    for (int o = 16; o > 0; o >>= 1) lm = fmaxf(lm, __shfl_xor_sync(0xffffffffu, lm, o));
    if ((t & 31) == 0) red[t >> 5] = lm;
    __syncthreads();
    if (t == 0) {
        float S = red[0];
        #pragma unroll
        for (int i = 1; i < 32; ++i) S = fmaxf(S, red[i]);
        red[32] = S;
    }
    __syncthreads();
    float S = red[32];

    // ---- phase B
    for (int j = e0 + t; j < e1; j += 1024) {
        int s  = g_csr16[j];
        int dl = g_csrd16[j] - n0;
        float dv = d_sl[dl];
        float x  = s_sl[s] + dv;
        float lg = (x > 0.f) ? x : 0.2f*x;
        float xm = S + dv;
        float m  = (xm > 0.f) ? xm : 0.2f*xm;
        float w  = __expf(lg - m);
        unsigned int bits = (__float_as_uint(w) + 0x400u) & 0xFFFFF800u;
        wp[j - e0] = bits | (unsigned int)s;
    }
    __syncthreads();

    // ---- phase C
    int warp = t >> 5, lane = t & 31;
    int g  = lane >> 3;
    int l8 = lane & 7;
    float2 bias2 = *(const float2*)(bias_g + hd*16 + 2*l8);
    const float* hbase = h_sl + 2*l8;

    for (int k = 0; k < 8; ++k) {
        int idx = k*128 + warp*4 + g;
        int nl  = g_order[n0 + idx];
        int j   = roff[nl];
        int r1  = roff[nl+1];
        unsigned long long a0 = 0ull, a1 = 0ull;
        float ws = 0.f;
        for (; j + 2 <= r1; j += 2) {
            unsigned int p0 = wp[j], p1 = wp[j+1];
            float w0 = __uint_as_float(p0 & 0xFFFFF800u);
            float w1 = __uint_as_float(p1 & 0xFFFFF800u);
            int s0 = p0 & 0x7FF, s1 = p1 & 0x7FF;
            unsigned long long h0 = *(const unsigned long long*)(hbase + s0*18);
            unsigned long long h1 = *(const unsigned long long*)(hbase + s1*18);
            fma2(a0, pack2(w0, w0), h0);
            fma2(a1, pack2(w1, w1), h1);
            ws += w0 + w1;
        }
        if (j < r1) {
            unsigned int p0 = wp[j];
            float w0 = __uint_as_float(p0 & 0xFFFFF800u);
            int s0 = p0 & 0x7FF;
            unsigned long long h0 = *(const unsigned long long*)(hbase + s0*18);
            fma2(a0, pack2(w0, w0), h0);
            ws += w0;
        }
        float ax, ay, bx, by;
        unpack2(ax, ay, a0);
        unpack2(bx, by, a1);
        float inv = (ws > 0.f) ? 1.0f/ws : 0.f;
        float kvx = (ax + bx)*inv + bias2.x;
        float kvy = (ay + by)*inv + bias2.y;
        int n = n0 + nl;
        size_t o = ((size_t)(b*NN + n))*64 + hd*16 + 2*l8;
        if (mode == 0) {
            *(float2*)(g_k + o)   = make_float2(kvx, kvy);
            *(float2*)(g_acc + o) = make_float2(kvx, kvy);
        } else if (mode == 1) {
            *(float2*)(g_k + o) = make_float2(kvx, kvy);
            float2 ac = *(float2*)(g_acc + o);
            *(float2*)(g_acc + o) = make_float2(ac.x + 2.f*kvx, ac.y + 2.f*kvy);
        } else {
            float2 ac = *(float2*)(g_acc + o);
            float2 yv = *(float2*)(g_y + o);
            *(float2*)(g_y + o) = make_float2(yv.x + DT6F*(ac.x + kvx),
                                              yv.y + DT6F*(ac.y + kvy));
        }
    }
}

// ---------------- output MLP -------------------------------------------------
__global__ void __launch_bounds__(256) k_out(const float* __restrict__ W1, const float* __restrict__ b1,
                                             const float* __restrict__ W2, const float* __restrict__ b2,
                                             float* __restrict__ out) {
    __shared__ float W1s[4096], W2s[4096];
    __shared__ float b1s[64], b2s[64];
    __shared__ float srow[8][136];
    int t = threadIdx.x;
    for (int i = t; i < 1024; i += 256) {
        ((float4*)W1s)[i] = ((const float4*)W1)[i];
        ((float4*)W2s)[i] = ((const float4*)W2)[i];
    }
    if (t < 64) { b1s[t] = b1[t]; b2s[t] = b2[t]; }
    __syncthreads();

    int warp = t >> 5, lane = t & 31, half = lane >> 4, hl = lane & 15;
    float* sr = &srow[warp][half*68];
    int rowbase = blockIdx.x*64 + warp*8;
    int j0 = hl*4;

    for (int it = 0; it < 4; ++it) {
        int gr = rowbase + it*2 + half;
        float4 v = ((const float4*)(g_y + (size_t)gr*64))[hl];
        sr[hl*4+0] = v.x; sr[hl*4+1] = v.y; sr[hl*4+2] = v.z; sr[hl*4+3] = v.w;
        __syncwarp();
        float4 a = make_float4(0.f, 0.f, 0.f, 0.f);
        #pragma unroll 8
        for (int i = 0; i < 64; ++i) {
            float rv = sr[i];
            float4 w4 = ((const float4*)(W1s + i*64))[hl];
            a.x += rv*w4.x; a.y += rv*w4.y; a.z += rv*w4.z; a.w += rv*w4.w;
        }
        a.x = tanhf(a.x + b1s[j0]);
        a.y = tanhf(a.y + b1s[j0+1]);
        a.z = tanhf(a.z + b1s[j0+2]);
        a.w = tanhf(a.w + b1s[j0+3]);
        __syncwarp();
        sr[hl*4+0] = a.x; sr[hl*4+1] = a.y; sr[hl*4+2] = a.z; sr[hl*4+3] = a.w;
        __syncwarp();
        float4 o = make_float4(0.f, 0.f, 0.f, 0.f);
        #pragma unroll 8
        for (int i = 0; i < 64; ++i) {
            float rv = sr[i];
            float4 w4 = ((const float4*)(W2s + i*64))[hl];
            o.x += rv*w4.x; o.y += rv*w4.y; o.z += rv*w4.z; o.w += rv*w4.w;
        }
        o.x += b2s[j0]; o.y += b2s[j0+1]; o.z += b2s[j0+2]; o.w += b2s[j0+3];
        ((float4*)(out + (size_t)gr*64))[hl] = o;
        __syncwarp();
    }
}

// ---------------- launch -----------------------------------------------------
extern "C" void kernel_launch(void* const* d_in, const int* in_sizes, int n_in,
                              void* d_out, int out_size) {
    const float* inputs = (const float*)d_in[0];
    const float* w_in   = (const float*)d_in[1];
    const float* b_in   = (const float*)d_in[2];
    const float* Wh     = (const float*)d_in[3];
    const float* bias_g = (const float*)d_in[4];
    const float* a_src  = (const float*)d_in[5];
    const float* a_dst  = (const float*)d_in[6];
    const float* w1     = (const float*)d_in[7];
    const float* b1     = (const float*)d_in[8];
    const float* w2     = (const float*)d_in[9];
    const float* b2     = (const float*)d_in[10];
    const int*   src    = (const int*)d_in[11];
    const int*   dst    = (const int*)d_in[12];
    float* out = (float*)d_out;

    cudaFuncSetAttribute(k_edge, cudaFuncAttributeMaxDynamicSharedMemorySize, SMEM_EDGE);
    cudaFuncSetAttribute(k_gemm, cudaFuncAttributeMaxDynamicSharedMemorySize, SMEM_GEMM);

    // launch index 3 = k_gemm (captured by ncu) — verifies split-K prediction
    k_input<<<(BB*NN*HH)/256, 256>>>(inputs, w_in, b_in);   // also zeros g_cnt
    k_hist<<<EE/256, 256>>>(dst);
    k_scan<<<1, 256>>>();
    k_gemm<<<512, 512, SMEM_GEMM>>>(Wh, a_src, a_dst, 0.f);
    k_fill<<<EE/256, 256>>>(src, dst);

    const float c2 = 0.05f;
    const float c4 = 0.1f;
    for (int s = 0; s < STEPS; ++s) {
        if (s != 0) k_gemm<<<512, 512, SMEM_GEMM>>>(Wh, a_src, a_dst, 0.f);
        k_edge<<<128, 1024, SMEM_EDGE>>>(bias_g, 0);
        k_gemm<<<512, 512, SMEM_GEMM>>>(Wh, a_src, a_dst, c2);
        k_edge<<<128, 1024, SMEM_EDGE>>>(bias_g, 1);
        k_gemm<<<512, 512, SMEM_GEMM>>>(Wh, a_src, a_dst, c2);
        k_edge<<<128, 1024, SMEM_EDGE>>>(bias_g, 1);
        k_gemm<<<512, 512, SMEM_GEMM>>>(Wh, a_src, a_dst, c4);
        k_edge<<<128, 1024, SMEM_EDGE>>>(bias_g, 2);
    }
    k_out<<<512, 256>>>(w1, b1, w2, b2, out);
}

// round 7
// speedup vs baseline: 3.0770x; 1.0914x over previous
#include <cuda_runtime.h>
#include <math.h>

#define BB 16
#define SS 12
#define NN 2048
#define HH 64
#define HEADS 4
#define DHD 16
#define EE 32768
#define STEPS 12
#define DT6F ((float)(0.1/6.0))

// ---------------- scratch ----------------------------------------------------
__device__ float g_y[BB*NN*HH];
__device__ float g_h[BB*HEADS*NN*DHD];     // [b][hd][n][16]
__device__ float g_es[BB*HEADS*NN];
__device__ float g_ed[BB*HEADS*NN];
__device__ float g_k[BB*NN*HH];
__device__ float g_acc[BB*NN*HH];
__device__ int   g_rowoff[NN+1];
__device__ int   g_cnt[NN];
__device__ int   g_cursor[NN];
__device__ int   g_order[NN];
__device__ unsigned short g_csr16[EE];
__device__ unsigned short g_csrd16[EE];

// ---------------- f32x2 helpers ----------------------------------------------
__device__ __forceinline__ void fma2(unsigned long long &d, unsigned long long a,
                                     unsigned long long b) {
    asm("fma.rn.f32x2 %0, %1, %2, %0;" : "+l"(d) : "l"(a), "l"(b));
}
__device__ __forceinline__ unsigned long long pack2(float lo, float hi) {
    unsigned long long r;
    asm("mov.b64 %0, {%1,%2};" : "=l"(r) : "f"(lo), "f"(hi));
    return r;
}
__device__ __forceinline__ void unpack2(float &lo, float &hi, unsigned long long v) {
    asm("mov.b64 {%0,%1}, %2;" : "=f"(lo), "=f"(hi) : "l"(v));
}

// ---------------- input projection + counter zero ----------------------------
__global__ void k_input(const float* __restrict__ inp, const float* __restrict__ w_in,
                        const float* __restrict__ b_in) {
    int idx = blockIdx.x*blockDim.x + threadIdx.x;
    if (idx < NN) g_cnt[idx] = 0;
    if (idx >= BB*NN*HH) return;
    int h  = idx & 63;
    int bn = idx >> 6;
    int b  = bn >> 11;
    int n  = bn & 2047;
    const float* ip = inp + ((size_t)(b*SS + 0)*NN + n)*2;
    g_y[idx] = ip[0]*w_in[h] + ip[1]*w_in[64+h] + b_in[h];
}

__global__ void k_hist(const int* __restrict__ dst) {
    int e = blockIdx.x*blockDim.x + threadIdx.x;
    if (e < EE) atomicAdd(&g_cnt[dst[e]], 1);
}

// scan + degree-sort (single block, 256 threads)
__global__ void k_scan() {
    __shared__ int part[256];
    __shared__ int dh[2][64];
    int t = threadIdx.x;
    if (t < 128) { dh[0][t & 63] = 0; dh[1][t & 63] = 0; }
    int base = t*8;
    int loc[8];
    int s = 0;
    #pragma unroll
    for (int i = 0; i < 8; ++i) { loc[i] = s; s += g_cnt[base+i]; }
    part[t] = s;
    __syncthreads();
    for (int off = 1; off < 256; off <<= 1) {
        int v = (t >= off) ? part[t-off] : 0;
        __syncthreads();
        part[t] += v;
        __syncthreads();
    }
    int excl = (t == 0) ? 0 : part[t-1];
    #pragma unroll
    for (int i = 0; i < 8; ++i) {
        int v = excl + loc[i];
        g_rowoff[base+i] = v;
        g_cursor[base+i] = v;
    }
    if (t == 255) g_rowoff[NN] = part[255];
    #pragma unroll
    for (int i = 0; i < 8; ++i) {
        int n = base + i;
        int d = min(g_cnt[n], 63);
        atomicAdd(&dh[n >> 10][d], 1);
    }
    __syncthreads();
    if (t < 2) {
        int acc = 0;
        for (int d = 0; d < 64; ++d) { int c = dh[t][d]; dh[t][d] = acc; acc += c; }
    }
    __syncthreads();
    #pragma unroll
    for (int i = 0; i < 8; ++i) {
        int n = base + i;
        int half = n >> 10;
        int d = min(g_cnt[n], 63);
        int pos = atomicAdd(&dh[half][d], 1);
        g_order[half*1024 + pos] = n & 1023;
    }
}

__global__ void k_fill(const int* __restrict__ src, const int* __restrict__ dst) {
    int e = blockIdx.x*blockDim.x + threadIdx.x;
    if (e < EE) {
        int d = dst[e];
        int p = atomicAdd(&g_cursor[d], 1);
        g_csr16[p]  = (unsigned short)src[e];
        g_csrd16[p] = (unsigned short)d;
    }
}

// ---------------- stage GEMM v4: register-blocked 8x8, row-pair f32x2 --------
// 128 threads, 128 rows/block, grid 256.
// smem: sd[64 pairs][65] ull (pad kills rg-bank conflicts)
//       Whd[i][k][c8][2] ull dup-weights (k-interleaved: conflict-free LDS.128)
//       As/Ad floats
#define SD_ULL   (64*65)
#define WHD_ULL  (64*4*8*2)
#define SMEM_GEMM ((SD_ULL + WHD_ULL)*8 + 128*4)

__global__ void __launch_bounds__(128, 3) k_gemm(const float* __restrict__ Wh,
                                                 const float* __restrict__ a_src,
                                                 const float* __restrict__ a_dst,
                                                 float coef) {
    extern __shared__ unsigned long long smg[];
    unsigned long long* sd  = smg;                 // 4160 ull
    unsigned long long* Whd = smg + SD_ULL;        // 4096 ull
    float* As = (float*)(smg + SD_ULL + WHD_ULL);  // 64
    float* Ad = As + 64;                           // 64

    int t = threadIdx.x;
    int rowbase = blockIdx.x*128;

    // stage Wh duplicated, k-interleaved layout
    #pragma unroll
    for (int it = 0; it < 8; ++it) {
        int idx = it*128 + t;                 // float4 index 0..1023
        int i  = idx >> 4;
        int c0 = (idx & 15)*4;
        float4 w = ((const float4*)Wh)[idx];
        float v[4] = {w.x, w.y, w.z, w.w};
        #pragma unroll
        for (int q = 0; q < 4; ++q) {
            int c = c0 + q;
            int c8i = c >> 3, kk = (c & 7) >> 1, sub = c & 1;
            Whd[((i*4 + kk)*8 + c8i)*2 + sub] = pack2(v[q], v[q]);
        }
    }
    if (t < 64) { As[t] = a_src[t]; Ad[t] = a_dst[t]; }

    // stage 128 rows as pairs (y[2p][i], y[2p+1][i])
    #pragma unroll
    for (int it = 0; it < 8; ++it) {
        int q  = it*128 + t;                  // 0..1023
        int p  = q >> 4;
        int i0 = (q & 15)*4;
        int gr = rowbase + p*2;
        float4 va = *(const float4*)(g_y + (size_t)gr*64 + i0);
        float4 vb = *(const float4*)(g_y + (size_t)(gr+1)*64 + i0);
        if (coef != 0.f) {
            float4 ka = *(const float4*)(g_k + (size_t)gr*64 + i0);
            float4 kb = *(const float4*)(g_k + (size_t)(gr+1)*64 + i0);
            va.x += coef*ka.x; va.y += coef*ka.y; va.z += coef*ka.z; va.w += coef*ka.w;
            vb.x += coef*kb.x; vb.y += coef*kb.y; vb.z += coef*kb.z; vb.w += coef*kb.w;
        }
        unsigned long long* d = sd + p*65 + i0;
        d[0] = pack2(va.x, vb.x); d[1] = pack2(va.y, vb.y);
        d[2] = pack2(va.z, vb.z); d[3] = pack2(va.w, vb.w);
    }
    __syncthreads();

    int c8 = t & 7, rg = t >> 3;              // cols c8*8..+8, rows rg*8..+8
    unsigned long long acc[4][8];
    #pragma unroll
    for (int p = 0; p < 4; ++p)
        #pragma unroll
        for (int c = 0; c < 8; ++c) acc[p][c] = 0ull;

    const unsigned long long* Rp = sd + rg*4*65;

    #pragma unroll 2
    for (int i = 0; i < 64; ++i) {
        unsigned long long r0 = Rp[i];
        unsigned long long r1 = Rp[65 + i];
        unsigned long long r2 = Rp[130 + i];
        unsigned long long r3 = Rp[195 + i];
        #pragma unroll
        for (int kk = 0; kk < 4; ++kk) {
            ulonglong2 w2 = *(const ulonglong2*)(Whd + ((i*4 + kk)*8 + c8)*2);
            fma2(acc[0][kk*2],   r0, w2.x); fma2(acc[0][kk*2+1], r0, w2.y);
            fma2(acc[1][kk*2],   r1, w2.x); fma2(acc[1][kk*2+1], r1, w2.y);
            fma2(acc[2][kk*2],   r2, w2.x); fma2(acc[2][kk*2+1], r2, w2.y);
            fma2(acc[3][kk*2],   r3, w2.x); fma2(acc[3][kk*2+1], r3, w2.y);
        }
    }

    // epilogue: h scatter + scores (partner lane c8^1 holds other dh half)
    int hd = c8 >> 1, dh0 = (c8 & 1)*8;
    float av[8], dv[8];
    #pragma unroll
    for (int c = 0; c < 8; ++c) {
        av[c] = As[hd*16 + dh0 + c];
        dv[c] = Ad[hd*16 + dh0 + c];
    }

    #pragma unroll
    for (int p = 0; p < 4; ++p) {
        float lo[8], hi[8];
        #pragma unroll
        for (int c = 0; c < 8; ++c) unpack2(lo[c], hi[c], acc[p][c]);

        #pragma unroll
        for (int rr = 0; rr < 2; ++rr) {
            float* v = rr ? hi : lo;
            int gr = rowbase + rg*8 + p*2 + rr;
            int bb = gr >> 11, n = gr & 2047;
            size_t hb = (((size_t)(bb*HEADS + hd))*NN + n)*DHD + dh0;
            *(float4*)(g_h + hb)     = make_float4(v[0], v[1], v[2], v[3]);
            *(float4*)(g_h + hb + 4) = make_float4(v[4], v[5], v[6], v[7]);
            float ps = v[0]*av[0] + v[1]*av[1] + v[2]*av[2] + v[3]*av[3]
                     + v[4]*av[4] + v[5]*av[5] + v[6]*av[6] + v[7]*av[7];
            float pd = v[0]*dv[0] + v[1]*dv[1] + v[2]*dv[2] + v[3]*dv[3]
                     + v[4]*dv[4] + v[5]*dv[5] + v[6]*dv[6] + v[7]*dv[7];
            ps += __shfl_xor_sync(0xffffffffu, ps, 1);
            pd += __shfl_xor_sync(0xffffffffu, pd, 1);
            if ((c8 & 1) == 0) {
                int o = (bb*HEADS + hd)*NN + n;
                g_es[o] = ps;
                g_ed[o] = pd;
            }
        }
    }
}

// ---------------- edge softmax + aggregation + RK4 bookkeeping ---------------
// smem words: h 2048*18 | s 2048 | d 1024 | roff 1025 | red 33 | wp 17024
#define W_CAP 17024
#define SMEM_EDGE ((2048*18 + 2048 + 1024 + 1025 + 33 + W_CAP)*4)

__global__ void __launch_bounds__(1024) k_edge(const float* __restrict__ bias_g, int mode) {
    extern __shared__ float sm[];
    float* h_sl = sm;                          // 2048*18
    float* s_sl = h_sl + 2048*18;              // 2048
    float* d_sl = s_sl + 2048;                 // 1024
    int*   roff = (int*)(d_sl + 1024);         // 1025
    float* red  = (float*)(roff + 1025);       // 33
    unsigned int* wp = (unsigned int*)(red + 33);  // 17024

    int t = threadIdx.x;
    int b  = blockIdx.x >> 3;
    int hd = (blockIdx.x >> 1) & 3;
    int halfblk = blockIdx.x & 1;
    int n0 = halfblk*1024;
    int sbase = (b*HEADS + hd)*NN;

    int e0 = g_rowoff[n0];
    int e1 = g_rowoff[n0 + 1024];

    // ---- phase A
    const float4* hp = (const float4*)(g_h + (size_t)sbase*DHD);
    for (int i = t; i < NN*DHD/4; i += 1024) {
        float4 v = hp[i];
        int p0 = i*4;
        float2* d = (float2*)(h_sl + (p0 >> 4)*18 + (p0 & 15));
        d[0] = make_float2(v.x, v.y);
        d[1] = make_float2(v.z, v.w);
    }
    float lm = -INFINITY;
    for (int i = t; i < NN; i += 1024) {
        float v = g_es[sbase + i];
        s_sl[i] = v;
        lm = fmaxf(lm, v);
    }
    d_sl[t] = g_ed[sbase + n0 + t];
    roff[t] = g_rowoff[n0 + t] - e0;
    if (t == 0) roff[1024] = e1 - e0;
    #pragma unroll
    for (int o = 16; o > 0; o >>= 1) lm = fmaxf(lm, __shfl_xor_sync(0xffffffffu, lm, o));
    if ((t & 31) == 0) red[t >> 5] = lm;
    __syncthreads();
    if (t == 0) {
        float S = red[0];
        #pragma unroll
        for (int i = 1; i < 32; ++i) S = fmaxf(S, red[i]);
        red[32] = S;
    }
    __syncthreads();
    float S = red[32];

    // ---- phase B
    for (int j = e0 + t; j < e1; j += 1024) {
        int s  = g_csr16[j];
        int dl = g_csrd16[j] - n0;
        float dv = d_sl[dl];
        float x  = s_sl[s] + dv;
        float lg = (x > 0.f) ? x : 0.2f*x;
        float xm = S + dv;
        float m  = (xm > 0.f) ? xm : 0.2f*xm;
        float w  = __expf(lg - m);
        unsigned int bits = (__float_as_uint(w) + 0x400u) & 0xFFFFF800u;
        wp[j - e0] = bits | (unsigned int)s;
    }
    __syncthreads();

    // ---- phase C
    int warp = t >> 5, lane = t & 31;
    int g  = lane >> 3;
    int l8 = lane & 7;
    float2 bias2 = *(const float2*)(bias_g + hd*16 + 2*l8);
    const float* hbase = h_sl + 2*l8;

    for (int k = 0; k < 8; ++k) {
        int idx = k*128 + warp*4 + g;
        int nl  = g_order[n0 + idx];
        int j   = roff[nl];
        int r1  = roff[nl+1];
        unsigned long long a0 = 0ull, a1 = 0ull;
        float ws = 0.f;
        for (; j + 2 <= r1; j += 2) {
            unsigned int p0 = wp[j], p1 = wp[j+1];
            float w0 = __uint_as_float(p0 & 0xFFFFF800u);
            float w1 = __uint_as_float(p1 & 0xFFFFF800u);
            int s0 = p0 & 0x7FF, s1 = p1 & 0x7FF;
            unsigned long long h0 = *(const unsigned long long*)(hbase + s0*18);
            unsigned long long h1 = *(const unsigned long long*)(hbase + s1*18);
            fma2(a0, pack2(w0, w0), h0);
            fma2(a1, pack2(w1, w1), h1);
            ws += w0 + w1;
        }
        if (j < r1) {
            unsigned int p0 = wp[j];
            float w0 = __uint_as_float(p0 & 0xFFFFF800u);
            int s0 = p0 & 0x7FF;
            unsigned long long h0 = *(const unsigned long long*)(hbase + s0*18);
            fma2(a0, pack2(w0, w0), h0);
            ws += w0;
        }
        float ax, ay, bx, by;
        unpack2(ax, ay, a0);
        unpack2(bx, by, a1);
        float inv = (ws > 0.f) ? 1.0f/ws : 0.f;
        float kvx = (ax + bx)*inv + bias2.x;
        float kvy = (ay + by)*inv + bias2.y;
        int n = n0 + nl;
        size_t o = ((size_t)(b*NN + n))*64 + hd*16 + 2*l8;
        if (mode == 0) {
            *(float2*)(g_k + o)   = make_float2(kvx, kvy);
            *(float2*)(g_acc + o) = make_float2(kvx, kvy);
        } else if (mode == 1) {
            *(float2*)(g_k + o) = make_float2(kvx, kvy);
            float2 ac = *(float2*)(g_acc + o);
            *(float2*)(g_acc + o) = make_float2(ac.x + 2.f*kvx, ac.y + 2.f*kvy);
        } else {
            float2 ac = *(float2*)(g_acc + o);
            float2 yv = *(float2*)(g_y + o);
            *(float2*)(g_y + o) = make_float2(yv.x + DT6F*(ac.x + kvx),
                                              yv.y + DT6F*(ac.y + kvy));
        }
    }
}

// ---------------- output MLP -------------------------------------------------
__global__ void __launch_bounds__(256) k_out(const float* __restrict__ W1, const float* __restrict__ b1,
                                             const float* __restrict__ W2, const float* __restrict__ b2,
                                             float* __restrict__ out) {
    __shared__ float W1s[4096], W2s[4096];
    __shared__ float b1s[64], b2s[64];
    __shared__ float srow[8][136];
    int t = threadIdx.x;
    for (int i = t; i < 1024; i += 256) {
        ((float4*)W1s)[i] = ((const float4*)W1)[i];
        ((float4*)W2s)[i] = ((const float4*)W2)[i];
    }
    if (t < 64) { b1s[t] = b1[t]; b2s[t] = b2[t]; }
    __syncthreads();

    int warp = t >> 5, lane = t & 31, half = lane >> 4, hl = lane & 15;
    float* sr = &srow[warp][half*68];
    int rowbase = blockIdx.x*64 + warp*8;
    int j0 = hl*4;

    for (int it = 0; it < 4; ++it) {
        int gr = rowbase + it*2 + half;
        float4 v = ((const float4*)(g_y + (size_t)gr*64))[hl];
        sr[hl*4+0] = v.x; sr[hl*4+1] = v.y; sr[hl*4+2] = v.z; sr[hl*4+3] = v.w;
        __syncwarp();
        float4 a = make_float4(0.f, 0.f, 0.f, 0.f);
        #pragma unroll 8
        for (int i = 0; i < 64; ++i) {
            float rv = sr[i];
            float4 w4 = ((const float4*)(W1s + i*64))[hl];
            a.x += rv*w4.x; a.y += rv*w4.y; a.z += rv*w4.z; a.w += rv*w4.w;
        }
        a.x = tanhf(a.x + b1s[j0]);
        a.y = tanhf(a.y + b1s[j0+1]);
        a.z = tanhf(a.z + b1s[j0+2]);
        a.w = tanhf(a.w + b1s[j0+3]);
        __syncwarp();
        sr[hl*4+0] = a.x; sr[hl*4+1] = a.y; sr[hl*4+2] = a.z; sr[hl*4+3] = a.w;
        __syncwarp();
        float4 o = make_float4(0.f, 0.f, 0.f, 0.f);
        #pragma unroll 8
        for (int i = 0; i < 64; ++i) {
            float rv = sr[i];
            float4 w4 = ((const float4*)(W2s + i*64))[hl];
            o.x += rv*w4.x; o.y += rv*w4.y; o.z += rv*w4.z; o.w += rv*w4.w;
        }
        o.x += b2s[j0]; o.y += b2s[j0+1]; o.z += b2s[j0+2]; o.w += b2s[j0+3];
        ((float4*)(out + (size_t)gr*64))[hl] = o;
        __syncwarp();
    }
}

// ---------------- launch -----------------------------------------------------
extern "C" void kernel_launch(void* const* d_in, const int* in_sizes, int n_in,
                              void* d_out, int out_size) {
    const float* inputs = (const float*)d_in[0];
    const float* w_in   = (const float*)d_in[1];
    const float* b_in   = (const float*)d_in[2];
    const float* Wh     = (const float*)d_in[3];
    const float* bias_g = (const float*)d_in[4];
    const float* a_src  = (const float*)d_in[5];
    const float* a_dst  = (const float*)d_in[6];
    const float* w1     = (const float*)d_in[7];
    const float* b1     = (const float*)d_in[8];
    const float* w2     = (const float*)d_in[9];
    const float* b2     = (const float*)d_in[10];
    const int*   src    = (const int*)d_in[11];
    const int*   dst    = (const int*)d_in[12];
    float* out = (float*)d_out;

    cudaFuncSetAttribute(k_edge, cudaFuncAttributeMaxDynamicSharedMemorySize, SMEM_EDGE);
    cudaFuncSetAttribute(k_gemm, cudaFuncAttributeMaxDynamicSharedMemorySize, SMEM_GEMM);

    // launch index 3 = k_gemm (captured by ncu)
    k_input<<<(BB*NN*HH)/256, 256>>>(inputs, w_in, b_in);   // also zeros g_cnt
    k_hist<<<EE/256, 256>>>(dst);
    k_scan<<<1, 256>>>();
    k_gemm<<<256, 128, SMEM_GEMM>>>(Wh, a_src, a_dst, 0.f);
    k_fill<<<EE/256, 256>>>(src, dst);

    const float c2 = 0.05f;
    const float c4 = 0.1f;
    for (int s = 0; s < STEPS; ++s) {
        if (s != 0) k_gemm<<<256, 128, SMEM_GEMM>>>(Wh, a_src, a_dst, 0.f);
        k_edge<<<128, 1024, SMEM_EDGE>>>(bias_g, 0);
        k_gemm<<<256, 128, SMEM_GEMM>>>(Wh, a_src, a_dst, c2);
        k_edge<<<128, 1024, SMEM_EDGE>>>(bias_g, 1);
        k_gemm<<<256, 128, SMEM_GEMM>>>(Wh, a_src, a_dst, c2);
        k_edge<<<128, 1024, SMEM_EDGE>>>(bias_g, 1);
        k_gemm<<<256, 128, SMEM_GEMM>>>(Wh, a_src, a_dst, c4);
        k_edge<<<128, 1024, SMEM_EDGE>>>(bias_g, 2);
    }
    k_out<<<512, 256>>>(w1, b1, w2, b2, out);
}

// round 8
// speedup vs baseline: 3.1119x; 1.0114x over previous
#include <cuda_runtime.h>
#include <math.h>

#define BB 16
#define SS 12
#define NN 2048
#define HH 64
#define HEADS 4
#define DHD 16
#define EE 32768
#define STEPS 12
#define DT6F ((float)(0.1/6.0))

// ---------------- scratch ----------------------------------------------------
__device__ float g_y[BB*NN*HH];
__device__ float g_h[BB*HEADS*NN*DHD];     // [b][hd][n][16]
__device__ float g_es[BB*HEADS*NN];
__device__ float g_ed[BB*HEADS*NN];
__device__ float g_k[BB*NN*HH];
__device__ float g_acc[BB*NN*HH];
__device__ int   g_rowoff[NN+1];
__device__ int   g_cnt[NN];
__device__ int   g_cursor[NN];
__device__ int   g_order[NN];
__device__ unsigned short g_csr16[EE];
__device__ unsigned short g_csrd16[EE];

// ---------------- f32x2 helpers ----------------------------------------------
__device__ __forceinline__ void fma2(unsigned long long &d, unsigned long long a,
                                     unsigned long long b) {
    asm("fma.rn.f32x2 %0, %1, %2, %0;" : "+l"(d) : "l"(a), "l"(b));
}
__device__ __forceinline__ unsigned long long pack2(float lo, float hi) {
    unsigned long long r;
    asm("mov.b64 %0, {%1,%2};" : "=l"(r) : "f"(lo), "f"(hi));
    return r;
}
__device__ __forceinline__ void unpack2(float &lo, float &hi, unsigned long long v) {
    asm("mov.b64 {%0,%1}, %2;" : "=f"(lo), "=f"(hi) : "l"(v));
}

// ---------------- input projection + counter zero ----------------------------
__global__ void k_input(const float* __restrict__ inp, const float* __restrict__ w_in,
                        const float* __restrict__ b_in) {
    int idx = blockIdx.x*blockDim.x + threadIdx.x;
    if (idx < NN) g_cnt[idx] = 0;
    if (idx >= BB*NN*HH) return;
    int h  = idx & 63;
    int bn = idx >> 6;
    int b  = bn >> 11;
    int n  = bn & 2047;
    const float* ip = inp + ((size_t)(b*SS + 0)*NN + n)*2;
    g_y[idx] = ip[0]*w_in[h] + ip[1]*w_in[64+h] + b_in[h];
}

__global__ void k_hist(const int* __restrict__ dst) {
    int e = blockIdx.x*blockDim.x + threadIdx.x;
    if (e < EE) atomicAdd(&g_cnt[dst[e]], 1);
}

// scan + degree-sort (single block, 256 threads)
__global__ void k_scan() {
    __shared__ int part[256];
    __shared__ int dh[2][64];
    int t = threadIdx.x;
    if (t < 128) { dh[0][t & 63] = 0; dh[1][t & 63] = 0; }
    int base = t*8;
    int loc[8];
    int s = 0;
    #pragma unroll
    for (int i = 0; i < 8; ++i) { loc[i] = s; s += g_cnt[base+i]; }
    part[t] = s;
    __syncthreads();
    for (int off = 1; off < 256; off <<= 1) {
        int v = (t >= off) ? part[t-off] : 0;
        __syncthreads();
        part[t] += v;
        __syncthreads();
    }
    int excl = (t == 0) ? 0 : part[t-1];
    #pragma unroll
    for (int i = 0; i < 8; ++i) {
        int v = excl + loc[i];
        g_rowoff[base+i] = v;
        g_cursor[base+i] = v;
    }
    if (t == 255) g_rowoff[NN] = part[255];
    #pragma unroll
    for (int i = 0; i < 8; ++i) {
        int n = base + i;
        int d = min(g_cnt[n], 63);
        atomicAdd(&dh[n >> 10][d], 1);
    }
    __syncthreads();
    if (t < 2) {
        int acc = 0;
        for (int d = 0; d < 64; ++d) { int c = dh[t][d]; dh[t][d] = acc; acc += c; }
    }
    __syncthreads();
    #pragma unroll
    for (int i = 0; i < 8; ++i) {
        int n = base + i;
        int half = n >> 10;
        int d = min(g_cnt[n], 63);
        int pos = atomicAdd(&dh[half][d], 1);
        g_order[half*1024 + pos] = n & 1023;
    }
}

__global__ void k_fill(const int* __restrict__ src, const int* __restrict__ dst) {
    int e = blockIdx.x*blockDim.x + threadIdx.x;
    if (e < EE) {
        int d = dst[e];
        int p = atomicAdd(&g_cursor[d], 1);
        g_csr16[p]  = (unsigned short)src[e];
        g_csrd16[p] = (unsigned short)d;
    }
}

// ---------------- stage GEMM v5: 256 thr, tile 8 rows x 4 cols ---------------
// smem: sd[64 pairs][65] ull | Whd[(i,q2)][c4] dup weights (4096 ull) | As/Ad
#define SD_ULL   (64*65)
#define WHD_ULL  (64*2*16*2)
#define SMEM_GEMM ((SD_ULL + WHD_ULL)*8 + 128*4)

__global__ void __launch_bounds__(256, 2) k_gemm(const float* __restrict__ Wh,
                                                 const float* __restrict__ a_src,
                                                 const float* __restrict__ a_dst,
                                                 float coef) {
    extern __shared__ unsigned long long smg[];
    unsigned long long* sd  = smg;                 // 4160 ull
    unsigned long long* Whd = smg + SD_ULL;        // 4096 ull
    float* As = (float*)(smg + SD_ULL + WHD_ULL);  // 64
    float* Ad = As + 64;                           // 64

    int t = threadIdx.x;
    int rowbase = blockIdx.x*128;

    // stage Wh duplicated: Whd[((i*2+q2)*16 + c4)*2 + su] = (w,w), c = c4*4+q2*2+su
    #pragma unroll
    for (int it = 0; it < 4; ++it) {
        int idx = it*256 + t;                 // float4 index 0..1023
        int i  = idx >> 4;
        int c0 = (idx & 15)*4;
        float4 w = ((const float4*)Wh)[idx];
        float v[4] = {w.x, w.y, w.z, w.w};
        #pragma unroll
        for (int q = 0; q < 4; ++q) {
            int c = c0 + q;
            int c4i = c >> 2, sub = c & 3;
            Whd[((i*2 + (sub >> 1))*16 + c4i)*2 + (sub & 1)] = pack2(v[q], v[q]);
        }
    }
    if (t < 64) { As[t] = a_src[t]; Ad[t] = a_dst[t]; }

    // stage 128 rows as pairs (y[2p][i], y[2p+1][i])
    #pragma unroll
    for (int it = 0; it < 4; ++it) {
        int q  = it*256 + t;                  // 0..1023
        int p  = q >> 4;
        int i0 = (q & 15)*4;
        int gr = rowbase + p*2;
        float4 va = *(const float4*)(g_y + (size_t)gr*64 + i0);
        float4 vb = *(const float4*)(g_y + (size_t)(gr+1)*64 + i0);
        if (coef != 0.f) {
            float4 ka = *(const float4*)(g_k + (size_t)gr*64 + i0);
            float4 kb = *(const float4*)(g_k + (size_t)(gr+1)*64 + i0);
            va.x += coef*ka.x; va.y += coef*ka.y; va.z += coef*ka.z; va.w += coef*ka.w;
            vb.x += coef*kb.x; vb.y += coef*kb.y; vb.z += coef*kb.z; vb.w += coef*kb.w;
        }
        unsigned long long* d = sd + p*65 + i0;
        d[0] = pack2(va.x, vb.x); d[1] = pack2(va.y, vb.y);
        d[2] = pack2(va.z, vb.z); d[3] = pack2(va.w, vb.w);
    }
    __syncthreads();

    int c4 = t & 15, rg = t >> 4;             // cols c4*4..+3, rows rg*8..+7
    unsigned long long acc[4][4];
    #pragma unroll
    for (int p = 0; p < 4; ++p)
        #pragma unroll
        for (int c = 0; c < 4; ++c) acc[p][c] = 0ull;

    const unsigned long long* Rp = sd + rg*4*65;
    const unsigned long long* Wp = Whd + c4*2;

    #pragma unroll 4
    for (int i = 0; i < 64; ++i) {
        unsigned long long r0 = Rp[i];
        unsigned long long r1 = Rp[65 + i];
        unsigned long long r2 = Rp[130 + i];
        unsigned long long r3 = Rp[195 + i];
        ulonglong2 w01 = *(const ulonglong2*)(Wp + (size_t)(i*2)*32);
        ulonglong2 w23 = *(const ulonglong2*)(Wp + (size_t)(i*2 + 1)*32);
        fma2(acc[0][0], r0, w01.x); fma2(acc[0][1], r0, w01.y);
        fma2(acc[0][2], r0, w23.x); fma2(acc[0][3], r0, w23.y);
        fma2(acc[1][0], r1, w01.x); fma2(acc[1][1], r1, w01.y);
        fma2(acc[1][2], r1, w23.x); fma2(acc[1][3], r1, w23.y);
        fma2(acc[2][0], r2, w01.x); fma2(acc[2][1], r2, w01.y);
        fma2(acc[2][2], r2, w23.x); fma2(acc[2][3], r2, w23.y);
        fma2(acc[3][0], r3, w01.x); fma2(acc[3][1], r3, w01.y);
        fma2(acc[3][2], r3, w23.x); fma2(acc[3][3], r3, w23.y);
    }

    // epilogue
    int hd = c4 >> 2, dh0 = (c4 & 3)*4;
    float4 av  = *(const float4*)(As + c4*4);
    float4 dvv = *(const float4*)(Ad + c4*4);

    #pragma unroll
    for (int pp = 0; pp < 4; ++pp) {
        float lo[4], hi[4];
        #pragma unroll
        for (int c = 0; c < 4; ++c) unpack2(lo[c], hi[c], acc[pp][c]);
        #pragma unroll
        for (int rr = 0; rr < 2; ++rr) {
            float* v = rr ? hi : lo;
            int gr = rowbase + rg*8 + pp*2 + rr;
            int bb = gr >> 11, n = gr & 2047;
            *(float4*)(g_h + (((size_t)(bb*HEADS + hd))*NN + n)*DHD + dh0)
                = make_float4(v[0], v[1], v[2], v[3]);
            float ps = v[0]*av.x + v[1]*av.y + v[2]*av.z + v[3]*av.w;
            float pd = v[0]*dvv.x + v[1]*dvv.y + v[2]*dvv.z + v[3]*dvv.w;
            ps += __shfl_xor_sync(0xffffffffu, ps, 1);
            ps += __shfl_xor_sync(0xffffffffu, ps, 2);
            pd += __shfl_xor_sync(0xffffffffu, pd, 1);
            pd += __shfl_xor_sync(0xffffffffu, pd, 2);
            if ((c4 & 3) == 0) {
                int o = (bb*HEADS + hd)*NN + n;
                g_es[o] = ps;
                g_ed[o] = pd;
            }
        }
    }
}

// ---------------- edge softmax + aggregation + RK4 bookkeeping ---------------
// smem words: h 2048*18 | s 2048 | d 1024 | roff 1025 | red 33 | wp 17024
#define W_CAP 17024
#define SMEM_EDGE ((2048*18 + 2048 + 1024 + 1025 + 33 + W_CAP)*4)

__global__ void __launch_bounds__(1024) k_edge(const float* __restrict__ bias_g, int mode) {
    extern __shared__ float sm[];
    float* h_sl = sm;                          // 2048*18
    float* s_sl = h_sl + 2048*18;              // 2048
    float* d_sl = s_sl + 2048;                 // 1024
    int*   roff = (int*)(d_sl + 1024);         // 1025
    float* red  = (float*)(roff + 1025);       // 33
    unsigned int* wp = (unsigned int*)(red + 33);  // 17024

    int t = threadIdx.x;
    int b  = blockIdx.x >> 3;
    int hd = (blockIdx.x >> 1) & 3;
    int halfblk = blockIdx.x & 1;
    int n0 = halfblk*1024;
    int sbase = (b*HEADS + hd)*NN;

    int e0 = g_rowoff[n0];
    int e1 = g_rowoff[n0 + 1024];

    // ---- phase A
    const float4* hp = (const float4*)(g_h + (size_t)sbase*DHD);
    for (int i = t; i < NN*DHD/4; i += 1024) {
        float4 v = hp[i];
        int p0 = i*4;
        float2* d = (float2*)(h_sl + (p0 >> 4)*18 + (p0 & 15));
        d[0] = make_float2(v.x, v.y);
        d[1] = make_float2(v.z, v.w);
    }
    float lm = -INFINITY;
    for (int i = t; i < NN; i += 1024) {
        float v = g_es[sbase + i];
        s_sl[i] = v;
        lm = fmaxf(lm, v);
    }
    d_sl[t] = g_ed[sbase + n0 + t];
    roff[t] = g_rowoff[n0 + t] - e0;
    if (t == 0) roff[1024] = e1 - e0;
    #pragma unroll
    for (int o = 16; o > 0; o >>= 1) lm = fmaxf(lm, __shfl_xor_sync(0xffffffffu, lm, o));
    if ((t & 31) == 0) red[t >> 5] = lm;
    __syncthreads();
    if (t == 0) {
        float S = red[0];
        #pragma unroll
        for (int i = 1; i < 32; ++i) S = fmaxf(S, red[i]);
        red[32] = S;
    }
    __syncthreads();
    float S = red[32];

    // ---- phase B
    for (int j = e0 + t; j < e1; j += 1024) {
        int s  = g_csr16[j];
        int dl = g_csrd16[j] - n0;
        float dv = d_sl[dl];
        float x  = s_sl[s] + dv;
        float lg = (x > 0.f) ? x : 0.2f*x;
        float xm = S + dv;
        float m  = (xm > 0.f) ? xm : 0.2f*xm;
        float w  = __expf(lg - m);
        unsigned int bits = (__float_as_uint(w) + 0x400u) & 0xFFFFF800u;
        wp[j - e0] = bits | (unsigned int)s;
    }
    __syncthreads();

    // ---- phase C
    int warp = t >> 5, lane = t & 31;
    int g  = lane >> 3;
    int l8 = lane & 7;
    float2 bias2 = *(const float2*)(bias_g + hd*16 + 2*l8);
    const float* hbase = h_sl + 2*l8;

    for (int k = 0; k < 8; ++k) {
        int idx = k*128 + warp*4 + g;
        int nl  = g_order[n0 + idx];
        int j   = roff[nl];
        int r1  = roff[nl+1];
        unsigned long long a0 = 0ull, a1 = 0ull;
        float ws = 0.f;
        for (; j + 2 <= r1; j += 2) {
            unsigned int p0 = wp[j], p1 = wp[j+1];
            float w0 = __uint_as_float(p0 & 0xFFFFF800u);
            float w1 = __uint_as_float(p1 & 0xFFFFF800u);
            int s0 = p0 & 0x7FF, s1 = p1 & 0x7FF;
            unsigned long long h0 = *(const unsigned long long*)(hbase + s0*18);
            unsigned long long h1 = *(const unsigned long long*)(hbase + s1*18);
            fma2(a0, pack2(w0, w0), h0);
            fma2(a1, pack2(w1, w1), h1);
            ws += w0 + w1;
        }
        if (j < r1) {
            unsigned int p0 = wp[j];
            float w0 = __uint_as_float(p0 & 0xFFFFF800u);
            int s0 = p0 & 0x7FF;
            unsigned long long h0 = *(const unsigned long long*)(hbase + s0*18);
            fma2(a0, pack2(w0, w0), h0);
            ws += w0;
        }
        float ax, ay, bx, by;
        unpack2(ax, ay, a0);
        unpack2(bx, by, a1);
        float inv = (ws > 0.f) ? 1.0f/ws : 0.f;
        float kvx = (ax + bx)*inv + bias2.x;
        float kvy = (ay + by)*inv + bias2.y;
        int n = n0 + nl;
        size_t o = ((size_t)(b*NN + n))*64 + hd*16 + 2*l8;
        if (mode == 0) {
            *(float2*)(g_k + o)   = make_float2(kvx, kvy);
            *(float2*)(g_acc + o) = make_float2(kvx, kvy);
        } else if (mode == 1) {
            *(float2*)(g_k + o) = make_float2(kvx, kvy);
            float2 ac = *(float2*)(g_acc + o);
            *(float2*)(g_acc + o) = make_float2(ac.x + 2.f*kvx, ac.y + 2.f*kvy);
        } else {
            float2 ac = *(float2*)(g_acc + o);
            float2 yv = *(float2*)(g_y + o);
            *(float2*)(g_y + o) = make_float2(yv.x + DT6F*(ac.x + kvx),
                                              yv.y + DT6F*(ac.y + kvy));
        }
    }
}

// ---------------- output MLP -------------------------------------------------
__global__ void __launch_bounds__(256) k_out(const float* __restrict__ W1, const float* __restrict__ b1,
                                             const float* __restrict__ W2, const float* __restrict__ b2,
                                             float* __restrict__ out) {
    __shared__ float W1s[4096], W2s[4096];
    __shared__ float b1s[64], b2s[64];
    __shared__ float srow[8][136];
    int t = threadIdx.x;
    for (int i = t; i < 1024; i += 256) {
        ((float4*)W1s)[i] = ((const float4*)W1)[i];
        ((float4*)W2s)[i] = ((const float4*)W2)[i];
    }
    if (t < 64) { b1s[t] = b1[t]; b2s[t] = b2[t]; }
    __syncthreads();

    int warp = t >> 5, lane = t & 31, half = lane >> 4, hl = lane & 15;
    float* sr = &srow[warp][half*68];
    int rowbase = blockIdx.x*64 + warp*8;
    int j0 = hl*4;

    for (int it = 0; it < 4; ++it) {
        int gr = rowbase + it*2 + half;
        float4 v = ((const float4*)(g_y + (size_t)gr*64))[hl];
        sr[hl*4+0] = v.x; sr[hl*4+1] = v.y; sr[hl*4+2] = v.z; sr[hl*4+3] = v.w;
        __syncwarp();
        float4 a = make_float4(0.f, 0.f, 0.f, 0.f);
        #pragma unroll 8
        for (int i = 0; i < 64; ++i) {
            float rv = sr[i];
            float4 w4 = ((const float4*)(W1s + i*64))[hl];
            a.x += rv*w4.x; a.y += rv*w4.y; a.z += rv*w4.z; a.w += rv*w4.w;
        }
        a.x = tanhf(a.x + b1s[j0]);
        a.y = tanhf(a.y + b1s[j0+1]);
        a.z = tanhf(a.z + b1s[j0+2]);
        a.w = tanhf(a.w + b1s[j0+3]);
        __syncwarp();
        sr[hl*4+0] = a.x; sr[hl*4+1] = a.y; sr[hl*4+2] = a.z; sr[hl*4+3] = a.w;
        __syncwarp();
        float4 o = make_float4(0.f, 0.f, 0.f, 0.f);
        #pragma unroll 8
        for (int i = 0; i < 64; ++i) {
            float rv = sr[i];
            float4 w4 = ((const float4*)(W2s + i*64))[hl];
            o.x += rv*w4.x; o.y += rv*w4.y; o.z += rv*w4.z; o.w += rv*w4.w;
        }
        o.x += b2s[j0]; o.y += b2s[j0+1]; o.z += b2s[j0+2]; o.w += b2s[j0+3];
        ((float4*)(out + (size_t)gr*64))[hl] = o;
        __syncwarp();
    }
}

// ---------------- launch -----------------------------------------------------
extern "C" void kernel_launch(void* const* d_in, const int* in_sizes, int n_in,
                              void* d_out, int out_size) {
    const float* inputs = (const float*)d_in[0];
    const float* w_in   = (const float*)d_in[1];
    const float* b_in   = (const float*)d_in[2];
    const float* Wh     = (const float*)d_in[3];
    const float* bias_g = (const float*)d_in[4];
    const float* a_src  = (const float*)d_in[5];
    const float* a_dst  = (const float*)d_in[6];
    const float* w1     = (const float*)d_in[7];
    const float* b1     = (const float*)d_in[8];
    const float* w2     = (const float*)d_in[9];
    const float* b2     = (const float*)d_in[10];
    const int*   src    = (const int*)d_in[11];
    const int*   dst    = (const int*)d_in[12];
    float* out = (float*)d_out;

    cudaFuncSetAttribute(k_edge, cudaFuncAttributeMaxDynamicSharedMemorySize, SMEM_EDGE);
    cudaFuncSetAttribute(k_gemm, cudaFuncAttributeMaxDynamicSharedMemorySize, SMEM_GEMM);

    // launch slot 4 (the profiled one) = k_edge DUMMY.
    // Dummy is deterministic + harmless: its g_k/g_acc outputs are fully
    // overwritten by the real mode-0 k_edge; first gemm uses coef=0 (no g_k read).
    k_input<<<(BB*NN*HH)/256, 256>>>(inputs, w_in, b_in);   // also zeros g_cnt
    k_hist<<<EE/256, 256>>>(dst);
    k_scan<<<1, 256>>>();
    k_edge<<<128, 1024, SMEM_EDGE>>>(bias_g, 0);            // DUMMY (profiled)
    k_fill<<<EE/256, 256>>>(src, dst);

    const float c2 = 0.05f;
    const float c4 = 0.1f;
    for (int s = 0; s < STEPS; ++s) {
        k_gemm<<<256, 256, SMEM_GEMM>>>(Wh, a_src, a_dst, 0.f);
        k_edge<<<128, 1024, SMEM_EDGE>>>(bias_g, 0);
        k_gemm<<<256, 256, SMEM_GEMM>>>(Wh, a_src, a_dst, c2);
        k_edge<<<128, 1024, SMEM_EDGE>>>(bias_g, 1);
        k_gemm<<<256, 256, SMEM_GEMM>>>(Wh, a_src, a_dst, c2);
        k_edge<<<128, 1024, SMEM_EDGE>>>(bias_g, 1);
        k_gemm<<<256, 256, SMEM_GEMM>>>(Wh, a_src, a_dst, c4);
        k_edge<<<128, 1024, SMEM_EDGE>>>(bias_g, 2);
    }
    k_out<<<512, 256>>>(w1, b1, w2, b2, out);
}

// round 9
// speedup vs baseline: 3.3038x; 1.0617x over previous
#include <cuda_runtime.h>
#include <math.h>

#define BB 16
#define SS 12
#define NN 2048
#define HH 64
#define HEADS 4
#define DHD 16
#define EE 32768
#define EPAD_MAX 40960
#define STEPS 12
#define DT6F ((float)(0.1/6.0))

// ---------------- scratch ----------------------------------------------------
__device__ float g_y[BB*NN*HH];
__device__ float g_h[BB*HEADS*NN*DHD];     // [b][hd][n][16]
__device__ float g_es[BB*HEADS*NN];
__device__ float g_ed[BB*HEADS*NN];
__device__ float g_k[BB*NN*HH];
__device__ float g_acc[BB*NN*HH];
__device__ int   g_rowoff[NN+1];           // PADDED (multiples of 4) offsets
__device__ int   g_cnt[NN];
__device__ int   g_cursor[NN];
__device__ int   g_order[NN];
__device__ unsigned int g_csrboth[EPAD_MAX]; // (dst<<16)|src ; 0xFFFFFFFF = pad

// ---------------- f32x2 helpers ----------------------------------------------
__device__ __forceinline__ void fma2(unsigned long long &d, unsigned long long a,
                                     unsigned long long b) {
    asm("fma.rn.f32x2 %0, %1, %2, %0;" : "+l"(d) : "l"(a), "l"(b));
}
__device__ __forceinline__ unsigned long long pack2(float lo, float hi) {
    unsigned long long r;
    asm("mov.b64 %0, {%1,%2};" : "=l"(r) : "f"(lo), "f"(hi));
    return r;
}
__device__ __forceinline__ void unpack2(float &lo, float &hi, unsigned long long v) {
    asm("mov.b64 {%0,%1}, %2;" : "=f"(lo), "=f"(hi) : "l"(v));
}

// ---------------- input projection + counter/sentinel init -------------------
__global__ void k_input(const float* __restrict__ inp, const float* __restrict__ w_in,
                        const float* __restrict__ b_in) {
    int idx = blockIdx.x*blockDim.x + threadIdx.x;
    if (idx < NN) g_cnt[idx] = 0;
    if (idx < EPAD_MAX) g_csrboth[idx] = 0xFFFFFFFFu;
    if (idx >= BB*NN*HH) return;
    int h  = idx & 63;
    int bn = idx >> 6;
    int b  = bn >> 11;
    int n  = bn & 2047;
    const float* ip = inp + ((size_t)(b*SS + 0)*NN + n)*2;
    g_y[idx] = ip[0]*w_in[h] + ip[1]*w_in[64+h] + b_in[h];
}

__global__ void k_hist(const int* __restrict__ dst) {
    int e = blockIdx.x*blockDim.x + threadIdx.x;
    if (e < EE) atomicAdd(&g_cnt[dst[e]], 1);
}

// scan (padded degrees) + degree-sort (single block, 256 threads)
__global__ void k_scan() {
    __shared__ int part[256];
    __shared__ int dh[2][64];
    int t = threadIdx.x;
    if (t < 128) { dh[0][t & 63] = 0; dh[1][t & 63] = 0; }
    int base = t*8;
    int loc[8];
    int s = 0;
    #pragma unroll
    for (int i = 0; i < 8; ++i) {
        loc[i] = s;
        s += (g_cnt[base+i] + 3) & ~3;       // pad each segment to mult of 4
    }
    part[t] = s;
    __syncthreads();
    for (int off = 1; off < 256; off <<= 1) {
        int v = (t >= off) ? part[t-off] : 0;
        __syncthreads();
        part[t] += v;
        __syncthreads();
    }
    int excl = (t == 0) ? 0 : part[t-1];
    #pragma unroll
    for (int i = 0; i < 8; ++i) {
        int v = excl + loc[i];
        g_rowoff[base+i] = v;
        g_cursor[base+i] = v;
    }
    if (t == 255) g_rowoff[NN] = part[255];
    #pragma unroll
    for (int i = 0; i < 8; ++i) {
        int n = base + i;
        int d = min(g_cnt[n], 63);
        atomicAdd(&dh[n >> 10][d], 1);
    }
    __syncthreads();
    if (t < 2) {
        int acc = 0;
        for (int d = 0; d < 64; ++d) { int c = dh[t][d]; dh[t][d] = acc; acc += c; }
    }
    __syncthreads();
    #pragma unroll
    for (int i = 0; i < 8; ++i) {
        int n = base + i;
        int half = n >> 10;
        int d = min(g_cnt[n], 63);
        int pos = atomicAdd(&dh[half][d], 1);
        g_order[half*1024 + pos] = n & 1023;
    }
}

__global__ void k_fill(const int* __restrict__ src, const int* __restrict__ dst) {
    int e = blockIdx.x*blockDim.x + threadIdx.x;
    if (e < EE) {
        int d = dst[e];
        int p = atomicAdd(&g_cursor[d], 1);
        g_csrboth[p] = ((unsigned int)d << 16) | (unsigned int)src[e];
    }
}

// ---------------- stage GEMM v5: 256 thr, tile 8 rows x 4 cols ---------------
#define SD_ULL   (64*65)
#define WHD_ULL  (64*2*16*2)
#define SMEM_GEMM ((SD_ULL + WHD_ULL)*8 + 128*4)

__global__ void __launch_bounds__(256, 2) k_gemm(const float* __restrict__ Wh,
                                                 const float* __restrict__ a_src,
                                                 const float* __restrict__ a_dst,
                                                 float coef) {
    extern __shared__ unsigned long long smg[];
    unsigned long long* sd  = smg;
    unsigned long long* Whd = smg + SD_ULL;
    float* As = (float*)(smg + SD_ULL + WHD_ULL);
    float* Ad = As + 64;

    int t = threadIdx.x;
    int rowbase = blockIdx.x*128;

    #pragma unroll
    for (int it = 0; it < 4; ++it) {
        int idx = it*256 + t;
        int i  = idx >> 4;
        int c0 = (idx & 15)*4;
        float4 w = ((const float4*)Wh)[idx];
        float v[4] = {w.x, w.y, w.z, w.w};
        #pragma unroll
        for (int q = 0; q < 4; ++q) {
            int c = c0 + q;
            int c4i = c >> 2, sub = c & 3;
            Whd[((i*2 + (sub >> 1))*16 + c4i)*2 + (sub & 1)] = pack2(v[q], v[q]);
        }
    }
    if (t < 64) { As[t] = a_src[t]; Ad[t] = a_dst[t]; }

    #pragma unroll
    for (int it = 0; it < 4; ++it) {
        int q  = it*256 + t;
        int p  = q >> 4;
        int i0 = (q & 15)*4;
        int gr = rowbase + p*2;
        float4 va = *(const float4*)(g_y + (size_t)gr*64 + i0);
        float4 vb = *(const float4*)(g_y + (size_t)(gr+1)*64 + i0);
        if (coef != 0.f) {
            float4 ka = *(const float4*)(g_k + (size_t)gr*64 + i0);
            float4 kb = *(const float4*)(g_k + (size_t)(gr+1)*64 + i0);
            va.x += coef*ka.x; va.y += coef*ka.y; va.z += coef*ka.z; va.w += coef*ka.w;
            vb.x += coef*kb.x; vb.y += coef*kb.y; vb.z += coef*kb.z; vb.w += coef*kb.w;
        }
        unsigned long long* d = sd + p*65 + i0;
        d[0] = pack2(va.x, vb.x); d[1] = pack2(va.y, vb.y);
        d[2] = pack2(va.z, vb.z); d[3] = pack2(va.w, vb.w);
    }
    __syncthreads();

    int c4 = t & 15, rg = t >> 4;
    unsigned long long acc[4][4];
    #pragma unroll
    for (int p = 0; p < 4; ++p)
        #pragma unroll
        for (int c = 0; c < 4; ++c) acc[p][c] = 0ull;

    const unsigned long long* Rp = sd + rg*4*65;
    const unsigned long long* Wp = Whd + c4*2;

    #pragma unroll 4
    for (int i = 0; i < 64; ++i) {
        unsigned long long r0 = Rp[i];
        unsigned long long r1 = Rp[65 + i];
        unsigned long long r2 = Rp[130 + i];
        unsigned long long r3 = Rp[195 + i];
        ulonglong2 w01 = *(const ulonglong2*)(Wp + (size_t)(i*2)*32);
        ulonglong2 w23 = *(const ulonglong2*)(Wp + (size_t)(i*2 + 1)*32);
        fma2(acc[0][0], r0, w01.x); fma2(acc[0][1], r0, w01.y);
        fma2(acc[0][2], r0, w23.x); fma2(acc[0][3], r0, w23.y);
        fma2(acc[1][0], r1, w01.x); fma2(acc[1][1], r1, w01.y);
        fma2(acc[1][2], r1, w23.x); fma2(acc[1][3], r1, w23.y);
        fma2(acc[2][0], r2, w01.x); fma2(acc[2][1], r2, w01.y);
        fma2(acc[2][2], r2, w23.x); fma2(acc[2][3], r2, w23.y);
        fma2(acc[3][0], r3, w01.x); fma2(acc[3][1], r3, w01.y);
        fma2(acc[3][2], r3, w23.x); fma2(acc[3][3], r3, w23.y);
    }

    int hd = c4 >> 2, dh0 = (c4 & 3)*4;
    float4 av  = *(const float4*)(As + c4*4);
    float4 dvv = *(const float4*)(Ad + c4*4);

    #pragma unroll
    for (int pp = 0; pp < 4; ++pp) {
        float lo[4], hi[4];
        #pragma unroll
        for (int c = 0; c < 4; ++c) unpack2(lo[c], hi[c], acc[pp][c]);
        #pragma unroll
        for (int rr = 0; rr < 2; ++rr) {
            float* v = rr ? hi : lo;
            int gr = rowbase + rg*8 + pp*2 + rr;
            int bb = gr >> 11, n = gr & 2047;
            *(float4*)(g_h + (((size_t)(bb*HEADS + hd))*NN + n)*DHD + dh0)
                = make_float4(v[0], v[1], v[2], v[3]);
            float ps = v[0]*av.x + v[1]*av.y + v[2]*av.z + v[3]*av.w;
            float pd = v[0]*dvv.x + v[1]*dvv.y + v[2]*dvv.z + v[3]*dvv.w;
            ps += __shfl_xor_sync(0xffffffffu, ps, 1);
            ps += __shfl_xor_sync(0xffffffffu, ps, 2);
            pd += __shfl_xor_sync(0xffffffffu, pd, 1);
            pd += __shfl_xor_sync(0xffffffffu, pd, 2);
            if ((c4 & 3) == 0) {
                int o = (bb*HEADS + hd)*NN + n;
                g_es[o] = ps;
                g_ed[o] = pd;
            }
        }
    }
}

// ---------------- edge softmax + aggregation + RK4 bookkeeping ---------------
// smem words: h 2048*16 | wp 19456 (16B-aligned) | s 2048 | d 1024 | roff 1025
//             | ord 1024 | red 33
#define W_CAP 19456
#define SMEM_EDGE ((2048*16 + W_CAP + 2048 + 1024 + 1025 + 1024 + 35)*4)

__global__ void __launch_bounds__(1024) k_edge(const float* __restrict__ bias_g, int mode) {
    extern __shared__ float sm[];
    float* h_sl = sm;                              // 2048*16 (natural layout)
    unsigned int* wp = (unsigned int*)(h_sl + 2048*16);  // 19456, 16B-aligned
    float* s_sl = (float*)(wp + W_CAP);            // 2048
    float* d_sl = s_sl + 2048;                     // 1024
    int*   roff = (int*)(d_sl + 1024);             // 1025
    int*   ord  = roff + 1025;                     // 1024
    float* red  = (float*)(ord + 1024);            // 33

    int t = threadIdx.x;
    int b  = blockIdx.x >> 3;
    int hd = (blockIdx.x >> 1) & 3;
    int halfblk = blockIdx.x & 1;
    int n0 = halfblk*1024;
    int sbase = (b*HEADS + hd)*NN;

    int e0 = g_rowoff[n0];                 // multiple of 4
    int e1 = g_rowoff[n0 + 1024];

    // ---- phase A: stage h (natural), scores, roff, order; block max src score
    const float4* hp = (const float4*)(g_h + (size_t)sbase*DHD);
    #pragma unroll
    for (int it = 0; it < 8; ++it)
        ((float4*)h_sl)[it*1024 + t] = hp[it*1024 + t];
    float lm = -INFINITY;
    #pragma unroll
    for (int it = 0; it < 2; ++it) {
        int i = it*1024 + t;
        float v = g_es[sbase + i];
        s_sl[i] = v;
        lm = fmaxf(lm, v);
    }
    d_sl[t] = g_ed[sbase + n0 + t];
    roff[t] = g_rowoff[n0 + t] - e0;
    ord[t]  = g_order[n0 + t];
    if (t == 0) roff[1024] = e1 - e0;
    #pragma unroll
    for (int o = 16; o > 0; o >>= 1) lm = fmaxf(lm, __shfl_xor_sync(0xffffffffu, lm, o));
    if ((t & 31) == 0) red[t >> 5] = lm;
    __syncthreads();
    if (t == 0) {
        float S = red[0];
        #pragma unroll
        for (int i = 1; i < 32; ++i) S = fmaxf(S, red[i]);
        red[32] = S;
    }
    __syncthreads();
    float S = red[32];

    // ---- phase B: per-edge weight, packed (w[31:11] | src[10:0]); pads -> 0
    for (int j = e0 + t; j < e1; j += 1024) {
        unsigned int p = g_csrboth[j];
        unsigned int w_out = 0u;
        if (p != 0xFFFFFFFFu) {
            int s  = (int)(p & 0xFFFFu);
            int dl = (int)(p >> 16) - n0;
            float dv = d_sl[dl];
            float x  = s_sl[s] + dv;
            float lg = (x > 0.f) ? x : 0.2f*x;
            float xm = S + dv;
            float m  = (xm > 0.f) ? xm : 0.2f*xm;
            float w  = __expf(lg - m);
            w_out = ((__float_as_uint(w) + 0x400u) & 0xFFFFF800u) | (unsigned int)s;
        }
        wp[j - e0] = w_out;
    }
    __syncthreads();

    // ---- phase C: 8 lanes/node, LDS.128 quads, scalar FFMA, no remainder ----
    int warp = t >> 5, lane = t & 31;
    int g  = lane >> 3;
    int l8 = lane & 7;
    float2 bias2 = *(const float2*)(bias_g + hd*16 + 2*l8);
    const float* hbase = h_sl + 2*l8;

    for (int k = 0; k < 8; ++k) {
        int idx = k*128 + warp*4 + g;
        int nl  = ord[idx];
        int j   = roff[nl];
        int r1  = roff[nl+1];
        float a0x=0.f,a0y=0.f,a1x=0.f,a1y=0.f;
        float a2x=0.f,a2y=0.f,a3x=0.f,a3y=0.f;
        float ws0=0.f, ws1=0.f;
        for (; j < r1; j += 4) {
            uint4 P = *(const uint4*)(wp + j);
            float w0 = __uint_as_float(P.x & 0xFFFFF800u);
            float w1 = __uint_as_float(P.y & 0xFFFFF800u);
            float w2 = __uint_as_float(P.z & 0xFFFFF800u);
            float w3 = __uint_as_float(P.w & 0xFFFFF800u);
            float2 h0 = *(const float2*)(hbase + (P.x & 0x7FFu)*16);
            float2 h1 = *(const float2*)(hbase + (P.y & 0x7FFu)*16);
            float2 h2 = *(const float2*)(hbase + (P.z & 0x7FFu)*16);
            float2 h3 = *(const float2*)(hbase + (P.w & 0x7FFu)*16);
            a0x = fmaf(w0, h0.x, a0x); a0y = fmaf(w0, h0.y, a0y);
            a1x = fmaf(w1, h1.x, a1x); a1y = fmaf(w1, h1.y, a1y);
            a2x = fmaf(w2, h2.x, a2x); a2y = fmaf(w2, h2.y, a2y);
            a3x = fmaf(w3, h3.x, a3x); a3y = fmaf(w3, h3.y, a3y);
            ws0 += w0 + w1;
            ws1 += w2 + w3;
        }
        float ax = (a0x + a1x) + (a2x + a3x);
        float ay = (a0y + a1y) + (a2y + a3y);
        float ws = ws0 + ws1;
        float inv = (ws > 0.f) ? 1.0f/ws : 0.f;
        float kvx = ax*inv + bias2.x;
        float kvy = ay*inv + bias2.y;
        int n = n0 + nl;
        size_t o = ((size_t)(b*NN + n))*64 + hd*16 + 2*l8;
        if (mode == 0) {
            *(float2*)(g_k + o)   = make_float2(kvx, kvy);
            *(float2*)(g_acc + o) = make_float2(kvx, kvy);
        } else if (mode == 1) {
            *(float2*)(g_k + o) = make_float2(kvx, kvy);
            float2 ac = *(float2*)(g_acc + o);
            *(float2*)(g_acc + o) = make_float2(ac.x + 2.f*kvx, ac.y + 2.f*kvy);
        } else {
            float2 ac = *(float2*)(g_acc + o);
            float2 yv = *(float2*)(g_y + o);
            *(float2*)(g_y + o) = make_float2(yv.x + DT6F*(ac.x + kvx),
                                              yv.y + DT6F*(ac.y + kvy));
        }
    }
}

// ---------------- output MLP -------------------------------------------------
__global__ void __launch_bounds__(256) k_out(const float* __restrict__ W1, const float* __restrict__ b1,
                                             const float* __restrict__ W2, const float* __restrict__ b2,
                                             float* __restrict__ out) {
    __shared__ float W1s[4096], W2s[4096];
    __shared__ float b1s[64], b2s[64];
    __shared__ float srow[8][136];
    int t = threadIdx.x;
    for (int i = t; i < 1024; i += 256) {
        ((float4*)W1s)[i] = ((const float4*)W1)[i];
        ((float4*)W2s)[i] = ((const float4*)W2)[i];
    }
    if (t < 64) { b1s[t] = b1[t]; b2s[t] = b2[t]; }
    __syncthreads();

    int warp = t >> 5, lane = t & 31, half = lane >> 4, hl = lane & 15;
    float* sr = &srow[warp][half*68];
    int rowbase = blockIdx.x*64 + warp*8;
    int j0 = hl*4;

    for (int it = 0; it < 4; ++it) {
        int gr = rowbase + it*2 + half;
        float4 v = ((const float4*)(g_y + (size_t)gr*64))[hl];
        sr[hl*4+0] = v.x; sr[hl*4+1] = v.y; sr[hl*4+2] = v.z; sr[hl*4+3] = v.w;
        __syncwarp();
        float4 a = make_float4(0.f, 0.f, 0.f, 0.f);
        #pragma unroll 8
        for (int i = 0; i < 64; ++i) {
            float rv = sr[i];
            float4 w4 = ((const float4*)(W1s + i*64))[hl];
            a.x += rv*w4.x; a.y += rv*w4.y; a.z += rv*w4.z; a.w += rv*w4.w;
        }
        a.x = tanhf(a.x + b1s[j0]);
        a.y = tanhf(a.y + b1s[j0+1]);
        a.z = tanhf(a.z + b1s[j0+2]);
        a.w = tanhf(a.w + b1s[j0+3]);
        __syncwarp();
        sr[hl*4+0] = a.x; sr[hl*4+1] = a.y; sr[hl*4+2] = a.z; sr[hl*4+3] = a.w;
        __syncwarp();
        float4 o = make_float4(0.f, 0.f, 0.f, 0.f);
        #pragma unroll 8
        for (int i = 0; i < 64; ++i) {
            float rv = sr[i];
            float4 w4 = ((const float4*)(W2s + i*64))[hl];
            o.x += rv*w4.x; o.y += rv*w4.y; o.z += rv*w4.z; o.w += rv*w4.w;
        }
        o.x += b2s[j0]; o.y += b2s[j0+1]; o.z += b2s[j0+2]; o.w += b2s[j0+3];
        ((float4*)(out + (size_t)gr*64))[hl] = o;
        __syncwarp();
    }
}

// ---------------- launch -----------------------------------------------------
extern "C" void kernel_launch(void* const* d_in, const int* in_sizes, int n_in,
                              void* d_out, int out_size) {
    const float* inputs = (const float*)d_in[0];
    const float* w_in   = (const float*)d_in[1];
    const float* b_in   = (const float*)d_in[2];
    const float* Wh     = (const float*)d_in[3];
    const float* bias_g = (const float*)d_in[4];
    const float* a_src  = (const float*)d_in[5];
    const float* a_dst  = (const float*)d_in[6];
    const float* w1     = (const float*)d_in[7];
    const float* b1     = (const float*)d_in[8];
    const float* w2     = (const float*)d_in[9];
    const float* b2     = (const float*)d_in[10];
    const int*   src    = (const int*)d_in[11];
    const int*   dst    = (const int*)d_in[12];
    float* out = (float*)d_out;

    cudaFuncSetAttribute(k_edge, cudaFuncAttributeMaxDynamicSharedMemorySize, SMEM_EDGE);
    cudaFuncSetAttribute(k_gemm, cudaFuncAttributeMaxDynamicSharedMemorySize, SMEM_GEMM);

    // launch slot 4 (profiled) = k_edge DUMMY — output fully overwritten later.
    k_input<<<(BB*NN*HH)/256, 256>>>(inputs, w_in, b_in);   // zeros cnt, sentinels csr
    k_hist<<<EE/256, 256>>>(dst);
    k_scan<<<1, 256>>>();
    k_edge<<<128, 1024, SMEM_EDGE>>>(bias_g, 0);            // DUMMY (profiled)
    k_fill<<<EE/256, 256>>>(src, dst);

    const float c2 = 0.05f;
    const float c4 = 0.1f;
    for (int s = 0; s < STEPS; ++s) {
        k_gemm<<<256, 256, SMEM_GEMM>>>(Wh, a_src, a_dst, 0.f);
        k_edge<<<128, 1024, SMEM_EDGE>>>(bias_g, 0);
        k_gemm<<<256, 256, SMEM_GEMM>>>(Wh, a_src, a_dst, c2);
        k_edge<<<128, 1024, SMEM_EDGE>>>(bias_g, 1);
        k_gemm<<<256, 256, SMEM_GEMM>>>(Wh, a_src, a_dst, c2);
        k_edge<<<128, 1024, SMEM_EDGE>>>(bias_g, 1);
        k_gemm<<<256, 256, SMEM_GEMM>>>(Wh, a_src, a_dst, c4);
        k_edge<<<128, 1024, SMEM_EDGE>>>(bias_g, 2);
    }
    k_out<<<512, 256>>>(w1, b1, w2, b2, out);
}

// round 10
// speedup vs baseline: 3.5719x; 1.0811x over previous
#include <cuda_runtime.h>
#include <math.h>

#define BB 16
#define SS 12
#define NN 2048
#define HH 64
#define HEADS 4
#define DHD 16
#define EE 32768
#define EPAD_MAX 40960
#define STEPS 12
#define DT6F ((float)(0.1/6.0))

// ---------------- scratch ----------------------------------------------------
__device__ float g_y[BB*NN*HH];
__device__ float g_h[BB*HEADS*NN*DHD];     // [b][hd][n][16]
__device__ float g_es[BB*HEADS*NN];
__device__ float g_ed[BB*HEADS*NN];
__device__ float g_k[BB*NN*HH];
__device__ float g_acc[BB*NN*HH];
__device__ int   g_rowoff[NN+1];           // PADDED (multiples of 4) offsets
__device__ int   g_cnt[NN];
__device__ int   g_cursor[NN];
__device__ int   g_order[NN];
__device__ unsigned int g_csrboth[EPAD_MAX]; // (dst<<16)|src ; 0xFFFFFFFF = pad

// ---------------- f32x2 helpers ----------------------------------------------
__device__ __forceinline__ void fma2(unsigned long long &d, unsigned long long a,
                                     unsigned long long b) {
    asm("fma.rn.f32x2 %0, %1, %2, %0;" : "+l"(d) : "l"(a), "l"(b));
}
__device__ __forceinline__ unsigned long long pack2(float lo, float hi) {
    unsigned long long r;
    asm("mov.b64 %0, {%1,%2};" : "=l"(r) : "f"(lo), "f"(hi));
    return r;
}
__device__ __forceinline__ void unpack2(float &lo, float &hi, unsigned long long v) {
    asm("mov.b64 {%0,%1}, %2;" : "=f"(lo), "=f"(hi) : "l"(v));
}

// ---------------- input projection + counter/sentinel init -------------------
__global__ void k_input(const float* __restrict__ inp, const float* __restrict__ w_in,
                        const float* __restrict__ b_in) {
    int idx = blockIdx.x*blockDim.x + threadIdx.x;
    if (idx < NN) g_cnt[idx] = 0;
    if (idx < EPAD_MAX) g_csrboth[idx] = 0xFFFFFFFFu;
    if (idx >= BB*NN*HH) return;
    int h  = idx & 63;
    int bn = idx >> 6;
    int b  = bn >> 11;
    int n  = bn & 2047;
    const float* ip = inp + ((size_t)(b*SS + 0)*NN + n)*2;
    g_y[idx] = ip[0]*w_in[h] + ip[1]*w_in[64+h] + b_in[h];
}

__global__ void k_hist(const int* __restrict__ dst) {
    int e = blockIdx.x*blockDim.x + threadIdx.x;
    if (e < EE) atomicAdd(&g_cnt[dst[e]], 1);
}

// scan (padded degrees) + degree-sort (single block, 256 threads)
__global__ void k_scan() {
    __shared__ int part[256];
    __shared__ int dh[2][64];
    int t = threadIdx.x;
    if (t < 128) { dh[0][t & 63] = 0; dh[1][t & 63] = 0; }
    int base = t*8;
    int loc[8];
    int s = 0;
    #pragma unroll
    for (int i = 0; i < 8; ++i) {
        loc[i] = s;
        s += (g_cnt[base+i] + 3) & ~3;       // pad each segment to mult of 4
    }
    part[t] = s;
    __syncthreads();
    for (int off = 1; off < 256; off <<= 1) {
        int v = (t >= off) ? part[t-off] : 0;
        __syncthreads();
        part[t] += v;
        __syncthreads();
    }
    int excl = (t == 0) ? 0 : part[t-1];
    #pragma unroll
    for (int i = 0; i < 8; ++i) {
        int v = excl + loc[i];
        g_rowoff[base+i] = v;
        g_cursor[base+i] = v;
    }
    if (t == 255) g_rowoff[NN] = part[255];
    #pragma unroll
    for (int i = 0; i < 8; ++i) {
        int n = base + i;
        int d = min(g_cnt[n], 63);
        atomicAdd(&dh[n >> 10][d], 1);
    }
    __syncthreads();
    if (t < 2) {
        int acc = 0;
        for (int d = 0; d < 64; ++d) { int c = dh[t][d]; dh[t][d] = acc; acc += c; }
    }
    __syncthreads();
    #pragma unroll
    for (int i = 0; i < 8; ++i) {
        int n = base + i;
        int half = n >> 10;
        int d = min(g_cnt[n], 63);
        int pos = atomicAdd(&dh[half][d], 1);
        g_order[half*1024 + pos] = n & 1023;
    }
}

__global__ void k_fill(const int* __restrict__ src, const int* __restrict__ dst) {
    int e = blockIdx.x*blockDim.x + threadIdx.x;
    if (e < EE) {
        int d = dst[e];
        int p = atomicAdd(&g_cursor[d], 1);
        g_csrboth[p] = ((unsigned int)d << 16) | (unsigned int)src[e];
    }
}

// ---------------- stage GEMM v6: 128 thr, tile 8 row-pairs x 4 cols ----------
// Weight LDS amortized over 16 rows/thread -> chip smem-wf ~1.3M (was 2.1M).
#define SD_ULL   (64*65)
#define WHD_ULL  (64*2*16*2)
#define SMEM_GEMM ((SD_ULL + WHD_ULL)*8 + 128*4)

__global__ void __launch_bounds__(128, 3) k_gemm(const float* __restrict__ Wh,
                                                 const float* __restrict__ a_src,
                                                 const float* __restrict__ a_dst,
                                                 float coef) {
    extern __shared__ unsigned long long smg[];
    unsigned long long* sd  = smg;                 // 64 pairs x 65
    unsigned long long* Whd = smg + SD_ULL;        // 4096
    float* As = (float*)(smg + SD_ULL + WHD_ULL);
    float* Ad = As + 64;

    int t = threadIdx.x;
    int rowbase = blockIdx.x*128;

    // stage Wh duplicated: Whd[((i*2+q2)*16 + c4)*2 + su], c = c4*4+q2*2+su
    #pragma unroll
    for (int it = 0; it < 8; ++it) {
        int idx = it*128 + t;                 // float4 index 0..1023
        int i  = idx >> 4;
        int c0 = (idx & 15)*4;
        float4 w = ((const float4*)Wh)[idx];
        float v[4] = {w.x, w.y, w.z, w.w};
        #pragma unroll
        for (int q = 0; q < 4; ++q) {
            int c = c0 + q;
            int c4i = c >> 2, sub = c & 3;
            Whd[((i*2 + (sub >> 1))*16 + c4i)*2 + (sub & 1)] = pack2(v[q], v[q]);
        }
    }
    if (t < 64) { As[t] = a_src[t]; Ad[t] = a_dst[t]; }

    // stage 128 rows as 64 pairs
    #pragma unroll
    for (int it = 0; it < 8; ++it) {
        int q  = it*128 + t;                  // 0..1023
        int p  = q >> 4;
        int i0 = (q & 15)*4;
        int gr = rowbase + p*2;
        float4 va = *(const float4*)(g_y + (size_t)gr*64 + i0);
        float4 vb = *(const float4*)(g_y + (size_t)(gr+1)*64 + i0);
        if (coef != 0.f) {
            float4 ka = *(const float4*)(g_k + (size_t)gr*64 + i0);
            float4 kb = *(const float4*)(g_k + (size_t)(gr+1)*64 + i0);
            va.x += coef*ka.x; va.y += coef*ka.y; va.z += coef*ka.z; va.w += coef*ka.w;
            vb.x += coef*kb.x; vb.y += coef*kb.y; vb.z += coef*kb.z; vb.w += coef*kb.w;
        }
        unsigned long long* d = sd + p*65 + i0;
        d[0] = pack2(va.x, vb.x); d[1] = pack2(va.y, vb.y);
        d[2] = pack2(va.z, vb.z); d[3] = pack2(va.w, vb.w);
    }
    __syncthreads();

    int c4 = t & 15, rg = t >> 4;             // cols c4*4..+3, pairs rg*8..+7
    unsigned long long acc[8][4];
    #pragma unroll
    for (int p = 0; p < 8; ++p)
        #pragma unroll
        for (int c = 0; c < 4; ++c) acc[p][c] = 0ull;

    const unsigned long long* Rp = sd + rg*8*65;
    const unsigned long long* Wp = Whd + c4*2;

    #pragma unroll 4
    for (int i = 0; i < 64; ++i) {
        ulonglong2 w01 = *(const ulonglong2*)(Wp + (size_t)(i*2)*32);
        ulonglong2 w23 = *(const ulonglong2*)(Wp + (size_t)(i*2 + 1)*32);
        #pragma unroll
        for (int p = 0; p < 8; ++p) {
            unsigned long long r = Rp[p*65 + i];
            fma2(acc[p][0], r, w01.x); fma2(acc[p][1], r, w01.y);
            fma2(acc[p][2], r, w23.x); fma2(acc[p][3], r, w23.y);
        }
    }

    int hd = c4 >> 2, dh0 = (c4 & 3)*4;
    float4 av  = *(const float4*)(As + c4*4);
    float4 dvv = *(const float4*)(Ad + c4*4);

    #pragma unroll
    for (int pp = 0; pp < 8; ++pp) {
        float lo[4], hi[4];
        #pragma unroll
        for (int c = 0; c < 4; ++c) unpack2(lo[c], hi[c], acc[pp][c]);
        #pragma unroll
        for (int rr = 0; rr < 2; ++rr) {
            float* v = rr ? hi : lo;
            int gr = rowbase + rg*16 + pp*2 + rr;
            int bb = gr >> 11, n = gr & 2047;
            *(float4*)(g_h + (((size_t)(bb*HEADS + hd))*NN + n)*DHD + dh0)
                = make_float4(v[0], v[1], v[2], v[3]);
            float ps = v[0]*av.x + v[1]*av.y + v[2]*av.z + v[3]*av.w;
            float pd = v[0]*dvv.x + v[1]*dvv.y + v[2]*dvv.z + v[3]*dvv.w;
            ps += __shfl_xor_sync(0xffffffffu, ps, 1);
            ps += __shfl_xor_sync(0xffffffffu, ps, 2);
            pd += __shfl_xor_sync(0xffffffffu, pd, 1);
            pd += __shfl_xor_sync(0xffffffffu, pd, 2);
            if ((c4 & 3) == 0) {
                int o = (bb*HEADS + hd)*NN + n;
                g_es[o] = ps;
                g_ed[o] = pd;
            }
        }
    }
}

// ---------------- edge softmax + aggregation + RK4 bookkeeping ---------------
// smem words: h 2048*16 | wp 19456 (16B-aligned) | s 2048 | d 1024 | roff 1025
//             | ord 1024 | red 33
#define W_CAP 19456
#define SMEM_EDGE ((2048*16 + W_CAP + 2048 + 1024 + 1025 + 1024 + 35)*4)

__global__ void __launch_bounds__(1024) k_edge(const float* __restrict__ bias_g, int mode) {
    extern __shared__ float sm[];
    float* h_sl = sm;                              // 2048*16 (natural layout)
    unsigned int* wp = (unsigned int*)(h_sl + 2048*16);  // 19456, 16B-aligned
    float* s_sl = (float*)(wp + W_CAP);            // 2048
    float* d_sl = s_sl + 2048;                     // 1024
    int*   roff = (int*)(d_sl + 1024);             // 1025
    int*   ord  = roff + 1025;                     // 1024
    float* red  = (float*)(ord + 1024);            // 33

    int t = threadIdx.x;
    int b  = blockIdx.x >> 3;
    int hd = (blockIdx.x >> 1) & 3;
    int halfblk = blockIdx.x & 1;
    int n0 = halfblk*1024;
    int sbase = (b*HEADS + hd)*NN;

    int e0 = g_rowoff[n0];                 // multiple of 4
    int e1 = g_rowoff[n0 + 1024];

    // ---- phase A: stage h (natural), scores, roff, order; block max src score
    const float4* hp = (const float4*)(g_h + (size_t)sbase*DHD);
    #pragma unroll
    for (int it = 0; it < 8; ++it)
        ((float4*)h_sl)[it*1024 + t] = hp[it*1024 + t];
    float lm = -INFINITY;
    #pragma unroll
    for (int it = 0; it < 2; ++it) {
        int i = it*1024 + t;
        float v = g_es[sbase + i];
        s_sl[i] = v;
        lm = fmaxf(lm, v);
    }
    d_sl[t] = g_ed[sbase + n0 + t];
    roff[t] = g_rowoff[n0 + t] - e0;
    ord[t]  = g_order[n0 + t];
    if (t == 0) roff[1024] = e1 - e0;
    #pragma unroll
    for (int o = 16; o > 0; o >>= 1) lm = fmaxf(lm, __shfl_xor_sync(0xffffffffu, lm, o));
    if ((t & 31) == 0) red[t >> 5] = lm;
    __syncthreads();
    if (t == 0) {
        float S = red[0];
        #pragma unroll
        for (int i = 1; i < 32; ++i) S = fmaxf(S, red[i]);
        red[32] = S;
    }
    __syncthreads();
    float S = red[32];

    // ---- phase B: per-edge weight packed (w[31:11] | src[10:0]); pads -> 0
    // NOTE: phase C reads the packed word AS the float weight (index bits stay
    // in the low mantissa; rel. noise <= 2^-12, consistent through wsum).
    for (int j = e0 + t; j < e1; j += 1024) {
        unsigned int p = g_csrboth[j];
        unsigned int w_out = 0u;
        if (p != 0xFFFFFFFFu) {
            int s  = (int)(p & 0xFFFFu);
            int dl = (int)(p >> 16) - n0;
            float dv = d_sl[dl];
            float x  = s_sl[s] + dv;
            float lg = (x > 0.f) ? x : 0.2f*x;
            float xm = S + dv;
            float m  = (xm > 0.f) ? xm : 0.2f*xm;
            float w  = __expf(lg - m);
            w_out = (__float_as_uint(w) & 0xFFFFF800u) | (unsigned int)s;
        }
        wp[j - e0] = w_out;
    }
    __syncthreads();

    // ---- phase C: 8 lanes/node, LDS.128 quads, no weight mask ----------------
    int warp = t >> 5, lane = t & 31;
    int g  = lane >> 3;
    int l8 = lane & 7;
    float2 bias2 = *(const float2*)(bias_g + hd*16 + 2*l8);
    const float* hbase = h_sl + 2*l8;

    for (int k = 0; k < 8; ++k) {
        int idx = k*128 + warp*4 + g;
        int nl  = ord[idx];
        int j   = roff[nl];
        int r1  = roff[nl+1];
        float a0x=0.f,a0y=0.f,a1x=0.f,a1y=0.f;
        float a2x=0.f,a2y=0.f,a3x=0.f,a3y=0.f;
        float ws0=0.f, ws1=0.f;
        for (; j < r1; j += 4) {
            uint4 P = *(const uint4*)(wp + j);
            float w0 = __uint_as_float(P.x);
            float w1 = __uint_as_float(P.y);
            float w2 = __uint_as_float(P.z);
            float w3 = __uint_as_float(P.w);
            float2 h0 = *(const float2*)(hbase + (P.x & 0x7FFu)*16);
            float2 h1 = *(const float2*)(hbase + (P.y & 0x7FFu)*16);
            float2 h2 = *(const float2*)(hbase + (P.z & 0x7FFu)*16);
            float2 h3 = *(const float2*)(hbase + (P.w & 0x7FFu)*16);
            a0x = fmaf(w0, h0.x, a0x); a0y = fmaf(w0, h0.y, a0y);
            a1x = fmaf(w1, h1.x, a1x); a1y = fmaf(w1, h1.y, a1y);
            a2x = fmaf(w2, h2.x, a2x); a2y = fmaf(w2, h2.y, a2y);
            a3x = fmaf(w3, h3.x, a3x); a3y = fmaf(w3, h3.y, a3y);
            ws0 += w0 + w1;
            ws1 += w2 + w3;
        }
        float ax = (a0x + a1x) + (a2x + a3x);
        float ay = (a0y + a1y) + (a2y + a3y);
        float ws = ws0 + ws1;
        float inv = (ws > 0.f) ? 1.0f/ws : 0.f;
        float kvx = ax*inv + bias2.x;
        float kvy = ay*inv + bias2.y;
        int n = n0 + nl;
        size_t o = ((size_t)(b*NN + n))*64 + hd*16 + 2*l8;
        if (mode == 0) {
            *(float2*)(g_k + o)   = make_float2(kvx, kvy);
            *(float2*)(g_acc + o) = make_float2(kvx, kvy);
        } else if (mode == 1) {
            *(float2*)(g_k + o) = make_float2(kvx, kvy);
            float2 ac = *(float2*)(g_acc + o);
            *(float2*)(g_acc + o) = make_float2(ac.x + 2.f*kvx, ac.y + 2.f*kvy);
        } else {
            float2 ac = *(float2*)(g_acc + o);
            float2 yv = *(float2*)(g_y + o);
            *(float2*)(g_y + o) = make_float2(yv.x + DT6F*(ac.x + kvx),
                                              yv.y + DT6F*(ac.y + kvy));
        }
    }
}

// ---------------- output MLP -------------------------------------------------
__global__ void __launch_bounds__(256) k_out(const float* __restrict__ W1, const float* __restrict__ b1,
                                             const float* __restrict__ W2, const float* __restrict__ b2,
                                             float* __restrict__ out) {
    __shared__ float W1s[4096], W2s[4096];
    __shared__ float b1s[64], b2s[64];
    __shared__ float srow[8][136];
    int t = threadIdx.x;
    for (int i = t; i < 1024; i += 256) {
        ((float4*)W1s)[i] = ((const float4*)W1)[i];
        ((float4*)W2s)[i] = ((const float4*)W2)[i];
    }
    if (t < 64) { b1s[t] = b1[t]; b2s[t] = b2[t]; }
    __syncthreads();

    int warp = t >> 5, lane = t & 31, half = lane >> 4, hl = lane & 15;
    float* sr = &srow[warp][half*68];
    int rowbase = blockIdx.x*64 + warp*8;
    int j0 = hl*4;

    for (int it = 0; it < 4; ++it) {
        int gr = rowbase + it*2 + half;
        float4 v = ((const float4*)(g_y + (size_t)gr*64))[hl];
        sr[hl*4+0] = v.x; sr[hl*4+1] = v.y; sr[hl*4+2] = v.z; sr[hl*4+3] = v.w;
        __syncwarp();
        float4 a = make_float4(0.f, 0.f, 0.f, 0.f);
        #pragma unroll 8
        for (int i = 0; i < 64; ++i) {
            float rv = sr[i];
            float4 w4 = ((const float4*)(W1s + i*64))[hl];
            a.x += rv*w4.x; a.y += rv*w4.y; a.z += rv*w4.z; a.w += rv*w4.w;
        }
        a.x = tanhf(a.x + b1s[j0]);
        a.y = tanhf(a.y + b1s[j0+1]);
        a.z = tanhf(a.z + b1s[j0+2]);
        a.w = tanhf(a.w + b1s[j0+3]);
        __syncwarp();
        sr[hl*4+0] = a.x; sr[hl*4+1] = a.y; sr[hl*4+2] = a.z; sr[hl*4+3] = a.w;
        __syncwarp();
        float4 o = make_float4(0.f, 0.f, 0.f, 0.f);
        #pragma unroll 8
        for (int i = 0; i < 64; ++i) {
            float rv = sr[i];
            float4 w4 = ((const float4*)(W2s + i*64))[hl];
            o.x += rv*w4.x; o.y += rv*w4.y; o.z += rv*w4.z; o.w += rv*w4.w;
        }
        o.x += b2s[j0]; o.y += b2s[j0+1]; o.z += b2s[j0+2]; o.w += b2s[j0+3];
        ((float4*)(out + (size_t)gr*64))[hl] = o;
        __syncwarp();
    }
}

// ---------------- launch -----------------------------------------------------
extern "C" void kernel_launch(void* const* d_in, const int* in_sizes, int n_in,
                              void* d_out, int out_size) {
    const float* inputs = (const float*)d_in[0];
    const float* w_in   = (const float*)d_in[1];
    const float* b_in   = (const float*)d_in[2];
    const float* Wh     = (const float*)d_in[3];
    const float* bias_g = (const float*)d_in[4];
    const float* a_src  = (const float*)d_in[5];
    const float* a_dst  = (const float*)d_in[6];
    const float* w1     = (const float*)d_in[7];
    const float* b1     = (const float*)d_in[8];
    const float* w2     = (const float*)d_in[9];
    const float* b2     = (const float*)d_in[10];
    const int*   src    = (const int*)d_in[11];
    const int*   dst    = (const int*)d_in[12];
    float* out = (float*)d_out;

    cudaFuncSetAttribute(k_edge, cudaFuncAttributeMaxDynamicSharedMemorySize, SMEM_EDGE);
    cudaFuncSetAttribute(k_gemm, cudaFuncAttributeMaxDynamicSharedMemorySize, SMEM_GEMM);

    // slot 4 (profiled) = first real k_gemm (v6) -> verifies crossbar model
    k_input<<<(BB*NN*HH)/256, 256>>>(inputs, w_in, b_in);   // zeros cnt, sentinels csr
    k_hist<<<EE/256, 256>>>(dst);
    k_scan<<<1, 256>>>();
    k_gemm<<<256, 128, SMEM_GEMM>>>(Wh, a_src, a_dst, 0.f);
    k_fill<<<EE/256, 256>>>(src, dst);

    const float c2 = 0.05f;
    const float c4 = 0.1f;
    for (int s = 0; s < STEPS; ++s) {
        if (s != 0) k_gemm<<<256, 128, SMEM_GEMM>>>(Wh, a_src, a_dst, 0.f);
        k_edge<<<128, 1024, SMEM_EDGE>>>(bias_g, 0);
        k_gemm<<<256, 128, SMEM_GEMM>>>(Wh, a_src, a_dst, c2);
        k_edge<<<128, 1024, SMEM_EDGE>>>(bias_g, 1);
        k_gemm<<<256, 128, SMEM_GEMM>>>(Wh, a_src, a_dst, c2);
        k_edge<<<128, 1024, SMEM_EDGE>>>(bias_g, 1);
        k_gemm<<<256, 128, SMEM_GEMM>>>(Wh, a_src, a_dst, c4);
        k_edge<<<128, 1024, SMEM_EDGE>>>(bias_g, 2);
    }
    k_out<<<512, 256>>>(w1, b1, w2, b2, out);
}